// round 1
// baseline (speedup 1.0000x reference)
#include <cuda_runtime.h>
#include <math.h>

// Problem constants: B=128, T=200, NC=3, NB=2, D=512, DH=256
#define NBOXES  153600          // B*T*NC*NB
#define NGROUPS 76800           // B*T*NC
#define GPB     600             // groups per batch (T*NC)
#define RPB     1800            // output rows per batch (600 dist + 1200 tok)

// ---- scratch (device globals: allocation-free contract) ----
__device__ float g_h[(size_t)NBOXES * 256];   // LN+gelu hidden, fp32
__device__ int   g_cat [NBOXES];
__device__ float g_conf[NBOXES];
__device__ float g_cx  [NBOXES];
__device__ float g_cy  [NBOXES];
__device__ float g_pres[NBOXES];

// ============================================================
// Kernel A: per-box prep. One warp per box.
//  - loads both boxes of the group, normalizes, presence, stable
//    2-element sort by (cat + (1-presence)*1000)
//  - geom[10] @ w1[10,256] + b1 -> LN -> exact gelu -> g_h
//  - meta for epilogue, dist token rows of the output
// ============================================================
__global__ void __launch_bounds__(256) prep_kernel(
    const float* __restrict__ box,
    const float* __restrict__ w1,  const float* __restrict__ b1,
    const float* __restrict__ lng, const float* __restrict__ lnb,
    const float* __restrict__ dw,  const float* __restrict__ db,
    float* __restrict__ out)
{
    int m    = blockIdx.x * 8 + (threadIdx.x >> 5);   // box index
    int lane = threadIdx.x & 31;
    int grp  = m >> 1;
    int jj   = m & 1;

    const float* p = box + (size_t)grp * 12;   // two raw boxes, 6 floats each
    float r0[6], r1[6];
#pragma unroll
    for (int i = 0; i < 6; i++) { r0[i] = __ldg(p + i); r1[i] = __ldg(p + 6 + i); }

    const float inw = 1.0f / 640.0f, inh = 1.0f / 400.0f;
    float c0x1 = r0[0]*inw, c0y1 = r0[1]*inh, c0x2 = r0[2]*inw, c0y2 = r0[3]*inh;
    float c1x1 = r1[0]*inw, c1y1 = r1[1]*inh, c1x2 = r1[2]*inw, c1y2 = r1[3]*inh;
    float s0 = c0x1 + c0y1 + c0x2 + c0y2;
    float s1 = c1x1 + c1y1 + c1x2 + c1y2;
    float pr0 = (s0 != 0.0f) ? 1.0f : 0.0f;
    float pr1 = (s1 != 0.0f) ? 1.0f : 0.0f;
    float k0 = r0[4] + (1.0f - pr0) * 1000.0f;
    float k1 = r1[4] + (1.0f - pr1) * 1000.0f;
    bool swp = (k1 < k0);                       // stable argsort of 2
    bool takeSecond = swp ? (jj == 0) : (jj == 1);

    float x1 = takeSecond ? c1x1 : c0x1;
    float y1 = takeSecond ? c1y1 : c0y1;
    float x2 = takeSecond ? c1x2 : c0x2;
    float y2 = takeSecond ? c1y2 : c0y2;
    float cat = takeSecond ? r1[4] : r0[4];
    float cf  = takeSecond ? r1[5] : r0[5];
    float pr  = takeSecond ? pr1  : pr0;

    float w  = x2 - x1, hh = y2 - y1;
    float cx = (x1 + x2) * 0.5f, cy = (y1 + y2) * 0.5f;
    float area = w * hh;
    float asp  = w / (hh + 1e-6f);
    float ge[10] = {x1, y1, x2, y2, w, hh, cx, cy, area, asp};

    // 10 -> 256 layer; lane handles d = i*32+lane
    float pre[8];
#pragma unroll
    for (int i = 0; i < 8; i++) {
        int d = i * 32 + lane;
        float acc = __ldg(b1 + d);
#pragma unroll
        for (int k = 0; k < 10; k++) acc = fmaf(ge[k], __ldg(w1 + k * 256 + d), acc);
        pre[i] = acc;
    }
    float s = pre[0]+pre[1]+pre[2]+pre[3]+pre[4]+pre[5]+pre[6]+pre[7];
#pragma unroll
    for (int o = 16; o > 0; o >>= 1) s += __shfl_xor_sync(0xffffffffu, s, o);
    float mu = s * (1.0f / 256.0f);
    float v = 0.0f;
#pragma unroll
    for (int i = 0; i < 8; i++) { float d0 = pre[i] - mu; v = fmaf(d0, d0, v); }
#pragma unroll
    for (int o = 16; o > 0; o >>= 1) v += __shfl_xor_sync(0xffffffffu, v, o);
    float inv = rsqrtf(v * (1.0f / 256.0f) + 1e-5f);

#pragma unroll
    for (int i = 0; i < 8; i++) {
        int d = i * 32 + lane;
        float x = (pre[i] - mu) * inv * __ldg(lng + d) + __ldg(lnb + d);
        float gl = 0.5f * x * (1.0f + erff(x * 0.70710678118654752440f)); // exact gelu
        g_h[(size_t)m * 256 + d] = gl;
    }

    if (lane == 0) {
        g_cat [m] = (int)cat;
        g_conf[m] = cf;
        g_cx  [m] = cx;
        g_cy  [m] = cy;
        g_pres[m] = pr;
    }

    // dist token row (one per group; invariant to the pair swap)
    if (jj == 0) {
        float cxa = (c0x1 + c0x2) * 0.5f, cya = (c0y1 + c0y2) * 0.5f;
        float cxb = (c1x1 + c1x2) * 0.5f, cyb = (c1y1 + c1y2) * 0.5f;
        float dx = cxa - cxb, dy = cya - cyb;
        float dist = sqrtf(dx * dx + dy * dy);
        int b  = grp / GPB;
        int gg = grp - b * GPB;
        float* orow = out + ((size_t)b * RPB + gg) * 512;
#pragma unroll
        for (int i = 0; i < 16; i++) {
            int n = i * 32 + lane;
            orow[n] = fmaf(dist, __ldg(dw + n), __ldg(db + n));
        }
    }
}

// ============================================================
// Kernel B: [153600,256] @ [256,512] fp32 GEMM via packed f32x2
// FFMA, fused embedding/scale/missing epilogue, direct output.
// Tiles: BM=128, BN=128, BK=16; 256 threads; 8x8 per thread.
// ============================================================
typedef unsigned long long u64;

__device__ __forceinline__ u64 pk2(float x) {
    u64 r; asm("mov.b64 %0, {%1, %1};" : "=l"(r) : "f"(x)); return r;
}
__device__ __forceinline__ void ffma2(u64& d, u64 a, u64 b) {
    asm("fma.rn.f32x2 %0, %1, %2, %0;" : "+l"(d) : "l"(a), "l"(b));
}
__device__ __forceinline__ float2 up2(u64 v) {
    float2 r; asm("mov.b64 {%0, %1}, %2;" : "=f"(r.x), "=f"(r.y) : "l"(v)); return r;
}

__global__ void __launch_bounds__(256) gemm_kernel(
    const float* __restrict__ w2,    const float* __restrict__ b2,
    const float* __restrict__ cat_table,
    const float* __restrict__ confw, const float* __restrict__ confb,
    const float* __restrict__ cw,    const float* __restrict__ cb,
    const float* __restrict__ miss,  const float* __restrict__ cam,
    const float* __restrict__ scale_p,
    float* __restrict__ out)
{
    __shared__ float As[2][16][132];   // transposed A tile (+pad)
    __shared__ float Bs[2][16][128];

    int tid = threadIdx.x;
    int tx = tid & 15, ty = tid >> 4;          // 16 x 16 thread grid
    int m0 = blockIdx.x * 128, n0 = blockIdx.y * 128;

    int ar = tid >> 2, ac = tid & 3;           // A load: rows ar, ar+64; col4 ac
    int bkr = tid >> 5, bc = tid & 31;         // B load: rows bkr, bkr+8; col4 bc

    const float* Abase = g_h + (size_t)m0 * 256;

    float4 a0, a1, bb0, bb1;
    // prologue: tile 0
    a0  = *(const float4*)(Abase + (size_t)ar * 256 + ac * 4);
    a1  = *(const float4*)(Abase + (size_t)(ar + 64) * 256 + ac * 4);
    bb0 = *(const float4*)(w2 + (size_t)bkr * 512 + n0 + bc * 4);
    bb1 = *(const float4*)(w2 + (size_t)(bkr + 8) * 512 + n0 + bc * 4);
    As[0][ac*4+0][ar]    = a0.x; As[0][ac*4+1][ar]    = a0.y;
    As[0][ac*4+2][ar]    = a0.z; As[0][ac*4+3][ar]    = a0.w;
    As[0][ac*4+0][ar+64] = a1.x; As[0][ac*4+1][ar+64] = a1.y;
    As[0][ac*4+2][ar+64] = a1.z; As[0][ac*4+3][ar+64] = a1.w;
    *(float4*)&Bs[0][bkr][bc*4]     = bb0;
    *(float4*)&Bs[0][bkr+8][bc*4]   = bb1;
    __syncthreads();

    u64 acc[8][4];
#pragma unroll
    for (int i = 0; i < 8; i++)
#pragma unroll
        for (int j = 0; j < 4; j++) acc[i][j] = 0ull;

    for (int kt = 0; kt < 16; ++kt) {
        int buf = kt & 1;
        if (kt < 15) {
            const float* Ak = Abase + (kt + 1) * 16 + ac * 4;
            a0  = *(const float4*)(Ak + (size_t)ar * 256);
            a1  = *(const float4*)(Ak + (size_t)(ar + 64) * 256);
            const float* Bk = w2 + (size_t)((kt + 1) * 16) * 512 + n0 + bc * 4;
            bb0 = *(const float4*)(Bk + (size_t)bkr * 512);
            bb1 = *(const float4*)(Bk + (size_t)(bkr + 8) * 512);
        }
#pragma unroll
        for (int k = 0; k < 16; k++) {
            float4 av0 = *(const float4*)&As[buf][k][ty * 8];
            float4 av1 = *(const float4*)&As[buf][k][ty * 8 + 4];
            const ulonglong2* bp2 = (const ulonglong2*)&Bs[buf][k][tx * 8];
            ulonglong2 q0 = bp2[0], q1 = bp2[1];
            u64 bp[4] = {q0.x, q0.y, q1.x, q1.y};
            u64 ap[8];
            ap[0] = pk2(av0.x); ap[1] = pk2(av0.y); ap[2] = pk2(av0.z); ap[3] = pk2(av0.w);
            ap[4] = pk2(av1.x); ap[5] = pk2(av1.y); ap[6] = pk2(av1.z); ap[7] = pk2(av1.w);
#pragma unroll
            for (int i = 0; i < 8; i++)
#pragma unroll
                for (int j = 0; j < 4; j++)
                    ffma2(acc[i][j], ap[i], bp[j]);
        }
        if (kt < 15) {
            int bw = buf ^ 1;
            As[bw][ac*4+0][ar]    = a0.x; As[bw][ac*4+1][ar]    = a0.y;
            As[bw][ac*4+2][ar]    = a0.z; As[bw][ac*4+3][ar]    = a0.w;
            As[bw][ac*4+0][ar+64] = a1.x; As[bw][ac*4+1][ar+64] = a1.y;
            As[bw][ac*4+2][ar+64] = a1.z; As[bw][ac*4+3][ar+64] = a1.w;
            *(float4*)&Bs[bw][bkr][bc*4]   = bb0;
            *(float4*)&Bs[bw][bkr+8][bc*4] = bb1;
            __syncthreads();
        }
    }

    // -------- epilogue: embeddings + scale + missing override --------
    float scl = __ldg(scale_p);
    int nb = n0 + tx * 8;
    float cwv[8], cw0v[8], cw1v[8], msv[8], cmb[8];
#pragma unroll
    for (int j = 0; j < 8; j++) {
        int n = nb + j;
        cwv[j]  = __ldg(confw + n);
        cw0v[j] = __ldg(cw + n);
        cw1v[j] = __ldg(cw + 512 + n);
        msv[j]  = __ldg(miss + n);
        cmb[j]  = __ldg(b2 + n) + __ldg(confb + n) + __ldg(cb + n);
    }
#pragma unroll
    for (int i = 0; i < 8; i++) {
        int m = m0 + ty * 8 + i;
        int catI = g_cat[m];
        float cf = g_conf[m], cxv = g_cx[m], cyv = g_cy[m], pr = g_pres[m];
        int grp  = m >> 1;
        int camI = grp % 3;
        int bI   = m / 1200;
        int rI   = m - bI * 1200;
        size_t orow = ((size_t)bI * RPB + 600 + rI) * 512;
        const float* ct  = cat_table + catI * 512 + nb;
        const float* cmr = cam + camI * 512 + nb;
        float o[8];
#pragma unroll
        for (int j = 0; j < 8; j++) {
            float2 p = up2(acc[i][j >> 1]);
            float g = (j & 1) ? p.y : p.x;
            float v = g + cmb[j] + __ldg(ct + j)
                    + cf * cwv[j] + cxv * cw0v[j] + cyv * cw1v[j]
                    + __ldg(cmr + j);
            v *= scl;
            o[j] = (pr == 0.0f) ? msv[j] : v;
        }
        *(float4*)(out + orow + nb)     = make_float4(o[0], o[1], o[2], o[3]);
        *(float4*)(out + orow + nb + 4) = make_float4(o[4], o[5], o[6], o[7]);
    }
}

// ============================================================
extern "C" void kernel_launch(void* const* d_in, const int* in_sizes, int n_in,
                              void* d_out, int out_size)
{
    const float* box   = (const float*)d_in[0];
    const float* catT  = (const float*)d_in[1];
    const float* w1    = (const float*)d_in[2];
    const float* b1    = (const float*)d_in[3];
    const float* lng   = (const float*)d_in[4];
    const float* lnb   = (const float*)d_in[5];
    const float* w2    = (const float*)d_in[6];
    const float* b2    = (const float*)d_in[7];
    const float* confw = (const float*)d_in[8];
    const float* confb = (const float*)d_in[9];
    const float* cw    = (const float*)d_in[10];
    const float* cb    = (const float*)d_in[11];
    const float* miss  = (const float*)d_in[12];
    const float* dw    = (const float*)d_in[13];
    const float* db    = (const float*)d_in[14];
    const float* cam   = (const float*)d_in[15];
    const float* scale = (const float*)d_in[16];
    float* out = (float*)d_out;

    prep_kernel<<<NBOXES / 8, 256>>>(box, w1, b1, lng, lnb, dw, db, out);

    dim3 grid(NBOXES / 128, 4);   // 1200 x 4
    gemm_kernel<<<grid, 256>>>(w2, b2, catT, confw, confb, cw, cb,
                               miss, cam, scale, out);
}

// round 3
// speedup vs baseline: 1.8489x; 1.8489x over previous
#include <cuda_runtime.h>
#include <cuda_bf16.h>
#include <math.h>
#include <stdint.h>

// Problem constants: B=128, T=200, NC=3, NB=2, D=512, DH=256
#define NBOXES  153600
#define GPB     600
#define RPB     1800

// ---------------- scratch ----------------
__device__ __nv_bfloat16 g_A[(size_t)NBOXES * 512];  // [m][0:256)=hi, [256:512)=lo
__device__ __nv_bfloat16 g_B[512 * 768];             // [n][0:256)=hi,[256:512)=hi,[512:768)=lo
__device__ float4        g_meta[NBOXES];             // {catI + 8*(missing), conf, cx, cy}
__device__ float         g_E[9 * 512];               // b2+confb+cb+catT[c]+cam[v]
__device__ float4        g_T4[512];                  // {confw, cw0, cw1, miss}

// ---------------- helpers ----------------
__device__ __forceinline__ uint32_t smem_u32(const void* p) {
    uint32_t a;
    asm("{ .reg .u64 t; cvta.to.shared.u64 t, %1; cvt.u32.u64 %0, t; }" : "=r"(a) : "l"(p));
    return a;
}
__device__ __forceinline__ void cpasync16(uint32_t s, const void* g) {
    asm volatile("cp.async.cg.shared.global [%0], [%1], 16;" :: "r"(s), "l"(g));
}
#define CP_COMMIT() asm volatile("cp.async.commit_group;" ::: "memory")
#define CP_WAIT(n)  asm volatile("cp.async.wait_group %0;" :: "n"(n) : "memory")

__device__ __forceinline__ void ldm_x4(uint32_t* r, uint32_t addr) {
    asm volatile("ldmatrix.sync.aligned.m8n8.x4.shared.b16 {%0,%1,%2,%3}, [%4];"
        : "=r"(r[0]), "=r"(r[1]), "=r"(r[2]), "=r"(r[3]) : "r"(addr));
}
__device__ __forceinline__ void mma16816(float* d, const uint32_t* a, uint32_t b0, uint32_t b1) {
    asm volatile(
        "mma.sync.aligned.m16n8k16.row.col.f32.bf16.bf16.f32 "
        "{%0,%1,%2,%3}, {%4,%5,%6,%7}, {%8,%9}, {%0,%1,%2,%3};"
        : "+f"(d[0]), "+f"(d[1]), "+f"(d[2]), "+f"(d[3])
        : "r"(a[0]), "r"(a[1]), "r"(a[2]), "r"(a[3]), "r"(b0), "r"(b1));
}

// ============================================================
// Kernel A: per-box prep (one warp per box).
// ============================================================
__global__ void __launch_bounds__(256) prep_kernel(
    const float* __restrict__ box,
    const float* __restrict__ w1,  const float* __restrict__ b1,
    const float* __restrict__ lng, const float* __restrict__ lnb,
    const float* __restrict__ dw,  const float* __restrict__ db,
    float* __restrict__ out)
{
    int m    = blockIdx.x * 8 + (threadIdx.x >> 5);
    int lane = threadIdx.x & 31;
    int grp  = m >> 1;
    int jj   = m & 1;

    const float* p = box + (size_t)grp * 12;
    float r0[6], r1[6];
#pragma unroll
    for (int i = 0; i < 6; i++) { r0[i] = __ldg(p + i); r1[i] = __ldg(p + 6 + i); }

    const float inw = 1.0f / 640.0f, inh = 1.0f / 400.0f;
    float c0x1 = r0[0]*inw, c0y1 = r0[1]*inh, c0x2 = r0[2]*inw, c0y2 = r0[3]*inh;
    float c1x1 = r1[0]*inw, c1y1 = r1[1]*inh, c1x2 = r1[2]*inw, c1y2 = r1[3]*inh;
    float s0 = c0x1 + c0y1 + c0x2 + c0y2;
    float s1 = c1x1 + c1y1 + c1x2 + c1y2;
    float pr0 = (s0 != 0.0f) ? 1.0f : 0.0f;
    float pr1 = (s1 != 0.0f) ? 1.0f : 0.0f;
    float k0 = r0[4] + (1.0f - pr0) * 1000.0f;
    float k1 = r1[4] + (1.0f - pr1) * 1000.0f;
    bool swp = (k1 < k0);
    bool takeSecond = swp ? (jj == 0) : (jj == 1);

    float x1 = takeSecond ? c1x1 : c0x1;
    float y1 = takeSecond ? c1y1 : c0y1;
    float x2 = takeSecond ? c1x2 : c0x2;
    float y2 = takeSecond ? c1y2 : c0y2;
    float cat = takeSecond ? r1[4] : r0[4];
    float cf  = takeSecond ? r1[5] : r0[5];
    float pr  = takeSecond ? pr1  : pr0;

    float w  = x2 - x1, hh = y2 - y1;
    float cx = (x1 + x2) * 0.5f, cy = (y1 + y2) * 0.5f;
    float area = w * hh;
    float asp  = w / (hh + 1e-6f);
    float ge[10] = {x1, y1, x2, y2, w, hh, cx, cy, area, asp};

    float pre[8];
#pragma unroll
    for (int i = 0; i < 8; i++) {
        int d = i * 32 + lane;
        float acc = __ldg(b1 + d);
#pragma unroll
        for (int k = 0; k < 10; k++) acc = fmaf(ge[k], __ldg(w1 + k * 256 + d), acc);
        pre[i] = acc;
    }
    float s = pre[0]+pre[1]+pre[2]+pre[3]+pre[4]+pre[5]+pre[6]+pre[7];
#pragma unroll
    for (int o = 16; o > 0; o >>= 1) s += __shfl_xor_sync(0xffffffffu, s, o);
    float mu = s * (1.0f / 256.0f);
    float v = 0.0f;
#pragma unroll
    for (int i = 0; i < 8; i++) { float d0 = pre[i] - mu; v = fmaf(d0, d0, v); }
#pragma unroll
    for (int o = 16; o > 0; o >>= 1) v += __shfl_xor_sync(0xffffffffu, v, o);
    float inv = rsqrtf(v * (1.0f / 256.0f) + 1e-5f);

    __nv_bfloat16* arow = g_A + (size_t)m * 512;
#pragma unroll
    for (int i = 0; i < 8; i++) {
        int d = i * 32 + lane;
        float x = (pre[i] - mu) * inv * __ldg(lng + d) + __ldg(lnb + d);
        float gl = 0.5f * x * (1.0f + erff(x * 0.70710678118654752440f));
        __nv_bfloat16 hi = __float2bfloat16(gl);
        float lo = gl - __bfloat162float(hi);
        arow[d]       = hi;
        arow[256 + d] = __float2bfloat16(lo);
    }

    if (lane == 0) {
        float pc = ((float)(int)cat) + ((pr == 0.0f) ? 8.0f : 0.0f);
        g_meta[m] = make_float4(pc, cf, cx, cy);
    }

    if (jj == 0) {
        float cxa = (c0x1 + c0x2) * 0.5f, cya = (c0y1 + c0y2) * 0.5f;
        float cxb = (c1x1 + c1x2) * 0.5f, cyb = (c1y1 + c1y2) * 0.5f;
        float dx = cxa - cxb, dy = cya - cyb;
        float dist = sqrtf(dx * dx + dy * dy);
        int b  = grp / GPB;
        int gg = grp - b * GPB;
        float* orow = out + ((size_t)b * RPB + gg) * 512;
#pragma unroll
        for (int i = 0; i < 16; i++) {
            int n = i * 32 + lane;
            orow[n] = fmaf(dist, __ldg(dw + n), __ldg(db + n));
        }
    }
}

// ============================================================
// Kernel W: split w2 into bf16 hi/hi/lo (K-major per n)
// ============================================================
__global__ void wprep_kernel(const float* __restrict__ w2)
{
    int n = blockIdx.x;      // 0..511
    int k = threadIdx.x;     // 0..255
    float x = __ldg(w2 + (size_t)k * 512 + n);
    __nv_bfloat16 hi = __float2bfloat16(x);
    float lo = x - __bfloat162float(hi);
    __nv_bfloat16* row = g_B + (size_t)n * 768;
    row[k]       = hi;
    row[256 + k] = hi;
    row[512 + k] = __float2bfloat16(lo);
}

// ============================================================
// Kernel E: epilogue tables. E[cat*3+cam][n], T4[n].
// ============================================================
__global__ void eprep_kernel(
    const float* __restrict__ b2,    const float* __restrict__ catT,
    const float* __restrict__ confw, const float* __restrict__ confb,
    const float* __restrict__ cw,    const float* __restrict__ cb,
    const float* __restrict__ miss,  const float* __restrict__ cam)
{
    int e = blockIdx.x;      // 0..9
    int n = threadIdx.x;     // 0..511
    if (e < 9) {
        int c = e / 3, v = e % 3;
        g_E[e * 512 + n] = __ldg(b2 + n) + __ldg(confb + n) + __ldg(cb + n)
                         + __ldg(catT + c * 512 + n) + __ldg(cam + v * 512 + n);
    } else {
        g_T4[n] = make_float4(__ldg(confw + n), __ldg(cw + n),
                              __ldg(cw + 512 + n), __ldg(miss + n));
    }
}

// ============================================================
// Kernel G: bf16 mma.sync GEMM [153600,768']x[768',512] (3-term
// split) + fused epilogue. BM=128, BN=128, BK=32, 8 warps.
// ============================================================
__global__ void __launch_bounds__(256, 2) gemm_kernel(
    const float* __restrict__ scale_p, float* __restrict__ out)
{
    __shared__ alignas(128) __nv_bfloat16 As[2][128][40];
    __shared__ alignas(128) __nv_bfloat16 Bs[2][128][40];

    int tid = threadIdx.x;
    int m0 = blockIdx.x * 128, n0 = blockIdx.y * 128;
    int warp = tid >> 5, lane = tid & 31;
    int wm = warp >> 1, wn = warp & 1;

    // per-stage loader: chunk c (0..23), stage s (0/1)
    int ldrow = tid >> 2, ldkc = (tid & 3) * 8;

    float acc[2][8][4];
#pragma unroll
    for (int i = 0; i < 2; i++)
#pragma unroll
        for (int j = 0; j < 8; j++)
#pragma unroll
            for (int v = 0; v < 4; v++) acc[i][j][v] = 0.0f;

    // fragment smem coordinates
    int arow  = wm * 32 + (lane & 15);
    int acol8 = (lane >> 4) * 8;
    int brow  = wn * 64 + (lane & 7) + (lane >> 4) * 8;
    int bcol8 = ((lane >> 3) & 1) * 8;

#define LOAD_STAGE(c, s) do {                                                   \
    int acol = ((c) < 16) ? (c) * 32 : (c) * 32 - 512;                          \
    const __nv_bfloat16* gA = g_A + (size_t)(m0 + ldrow) * 512 + acol + ldkc;   \
    const __nv_bfloat16* gB = g_B + (size_t)(n0 + ldrow) * 768 + (c) * 32 + ldkc;\
    cpasync16(smem_u32(&As[s][ldrow][ldkc]),      gA);                          \
    cpasync16(smem_u32(&As[s][ldrow + 64][ldkc]), gA + (size_t)64 * 512);       \
    cpasync16(smem_u32(&Bs[s][ldrow][ldkc]),      gB);                          \
    cpasync16(smem_u32(&Bs[s][ldrow + 64][ldkc]), gB + (size_t)64 * 768);       \
    CP_COMMIT();                                                                \
} while (0)

    LOAD_STAGE(0, 0);

    for (int c = 0; c < 24; c++) {
        int s = c & 1;
        if (c < 23) {
            LOAD_STAGE(c + 1, s ^ 1);
            CP_WAIT(1);
        } else {
            CP_WAIT(0);
        }
        __syncthreads();

#pragma unroll
        for (int ks = 0; ks < 2; ks++) {
            uint32_t a[2][4], b[4][4];
#pragma unroll
            for (int ti = 0; ti < 2; ti++)
                ldm_x4(a[ti], smem_u32(&As[s][arow + ti * 16][acol8 + ks * 16]));
#pragma unroll
            for (int jp = 0; jp < 4; jp++)
                ldm_x4(b[jp], smem_u32(&Bs[s][brow + jp * 16][bcol8 + ks * 16]));
#pragma unroll
            for (int ti = 0; ti < 2; ti++)
#pragma unroll
                for (int jp = 0; jp < 4; jp++) {
                    mma16816(acc[ti][jp * 2],     a[ti], b[jp][0], b[jp][1]);
                    mma16816(acc[ti][jp * 2 + 1], a[ti], b[jp][2], b[jp][3]);
                }
        }
        __syncthreads();
    }

    // ---------------- epilogue ----------------
    float scl = __ldg(scale_p);
    int lane4 = lane >> 2;
    int colp  = (lane & 3) * 2;

#pragma unroll
    for (int ti = 0; ti < 2; ti++) {
        int mA = m0 + wm * 32 + ti * 16 + lane4;
        int mB = mA + 8;
        float4 mtA = g_meta[mA];
        float4 mtB = g_meta[mB];
        int pcA = (int)mtA.x, pcB = (int)mtB.x;
        const float* eA = g_E + (size_t)((pcA & 3) * 3 + ((mA >> 1) % 3)) * 512;
        const float* eB = g_E + (size_t)((pcB & 3) * 3 + ((mB >> 1) % 3)) * 512;
        bool msA = (pcA >= 8), msB = (pcB >= 8);
        int bA = mA / 1200, rA = mA - bA * 1200;
        int bB = mB / 1200, rB = mB - bB * 1200;
        float* oA = out + ((size_t)bA * RPB + 600 + rA) * 512;
        float* oB = out + ((size_t)bB * RPB + 600 + rB) * 512;

#pragma unroll
        for (int j = 0; j < 8; j++) {
            int n = n0 + wn * 64 + j * 8 + colp;
            float4 t0 = g_T4[n], t1 = g_T4[n + 1];
            float v0 = (acc[ti][j][0] + eA[n]     + mtA.y * t0.x + mtA.z * t0.y + mtA.w * t0.z) * scl;
            float v1 = (acc[ti][j][1] + eA[n + 1] + mtA.y * t1.x + mtA.z * t1.y + mtA.w * t1.z) * scl;
            if (msA) { v0 = t0.w; v1 = t1.w; }
            *(float2*)(oA + n) = make_float2(v0, v1);

            float u0 = (acc[ti][j][2] + eB[n]     + mtB.y * t0.x + mtB.z * t0.y + mtB.w * t0.z) * scl;
            float u1 = (acc[ti][j][3] + eB[n + 1] + mtB.y * t1.x + mtB.z * t1.y + mtB.w * t1.z) * scl;
            if (msB) { u0 = t0.w; u1 = t1.w; }
            *(float2*)(oB + n) = make_float2(u0, u1);
        }
    }
#undef LOAD_STAGE
}

// ============================================================
extern "C" void kernel_launch(void* const* d_in, const int* in_sizes, int n_in,
                              void* d_out, int out_size)
{
    const float* box   = (const float*)d_in[0];
    const float* catT  = (const float*)d_in[1];
    const float* w1    = (const float*)d_in[2];
    const float* b1    = (const float*)d_in[3];
    const float* lng   = (const float*)d_in[4];
    const float* lnb   = (const float*)d_in[5];
    const float* w2    = (const float*)d_in[6];
    const float* b2    = (const float*)d_in[7];
    const float* confw = (const float*)d_in[8];
    const float* confb = (const float*)d_in[9];
    const float* cw    = (const float*)d_in[10];
    const float* cb    = (const float*)d_in[11];
    const float* miss  = (const float*)d_in[12];
    const float* dw    = (const float*)d_in[13];
    const float* db    = (const float*)d_in[14];
    const float* cam   = (const float*)d_in[15];
    const float* scale = (const float*)d_in[16];
    float* out = (float*)d_out;

    wprep_kernel<<<512, 256>>>(w2);
    eprep_kernel<<<10, 512>>>(b2, catT, confw, confb, cw, cb, miss, cam);
    prep_kernel<<<NBOXES / 8, 256>>>(box, w1, b1, lng, lnb, dw, db, out);

    dim3 grid(NBOXES / 128, 4);   // 1200 x 4
    gemm_kernel<<<grid, 256>>>(scale, out);
}

// round 4
// speedup vs baseline: 1.8944x; 1.0246x over previous
#include <cuda_runtime.h>
#include <cuda_bf16.h>
#include <math.h>
#include <stdint.h>

// Problem constants: B=128, T=200, NC=3, NB=2, D=512, DH=256
#define NBOXES  153600
#define GPB     600
#define RPB     1800

// ---------------- scratch ----------------
__device__ __nv_bfloat16 g_A[(size_t)NBOXES * 512];  // [m][0:256)=hi, [256:512)=lo
__device__ __nv_bfloat16 g_B[512 * 768];             // [n][0:256)=hi,[256:512)=hi,[512:768)=lo
__device__ float4        g_meta[NBOXES];             // {catI + 8*(missing), conf, cx, cy}
__device__ float         g_E[9 * 512];               // b2+confb+cb+catT[c]+cam[v]
__device__ float4        g_T4[512];                  // {confw, cw0, cw1, miss}

// ---------------- helpers ----------------
__device__ __forceinline__ uint32_t smem_u32(const void* p) {
    uint32_t a;
    asm("{ .reg .u64 t; cvta.to.shared.u64 t, %1; cvt.u32.u64 %0, t; }" : "=r"(a) : "l"(p));
    return a;
}
__device__ __forceinline__ void cpasync16(uint32_t s, const void* g) {
    asm volatile("cp.async.cg.shared.global [%0], [%1], 16;" :: "r"(s), "l"(g));
}
#define CP_COMMIT() asm volatile("cp.async.commit_group;" ::: "memory")
#define CP_WAIT(n)  asm volatile("cp.async.wait_group %0;" :: "n"(n) : "memory")

__device__ __forceinline__ void ldm_x4(uint32_t* r, uint32_t addr) {
    asm volatile("ldmatrix.sync.aligned.m8n8.x4.shared.b16 {%0,%1,%2,%3}, [%4];"
        : "=r"(r[0]), "=r"(r[1]), "=r"(r[2]), "=r"(r[3]) : "r"(addr));
}
__device__ __forceinline__ void mma16816(float* d, const uint32_t* a, uint32_t b0, uint32_t b1) {
    asm volatile(
        "mma.sync.aligned.m16n8k16.row.col.f32.bf16.bf16.f32 "
        "{%0,%1,%2,%3}, {%4,%5,%6,%7}, {%8,%9}, {%0,%1,%2,%3};"
        : "+f"(d[0]), "+f"(d[1]), "+f"(d[2]), "+f"(d[3])
        : "r"(a[0]), "r"(a[1]), "r"(a[2]), "r"(a[3]), "r"(b0), "r"(b1));
}

// ============================================================
// Kernel A: per-box prep (one warp per box).
// ============================================================
__global__ void __launch_bounds__(256) prep_kernel(
    const float* __restrict__ box,
    const float* __restrict__ w1,  const float* __restrict__ b1,
    const float* __restrict__ lng, const float* __restrict__ lnb,
    const float* __restrict__ dw,  const float* __restrict__ db,
    float* __restrict__ out)
{
    int m    = blockIdx.x * 8 + (threadIdx.x >> 5);
    int lane = threadIdx.x & 31;
    int grp  = m >> 1;
    int jj   = m & 1;

    const float* p = box + (size_t)grp * 12;
    float r0[6], r1[6];
#pragma unroll
    for (int i = 0; i < 6; i++) { r0[i] = __ldg(p + i); r1[i] = __ldg(p + 6 + i); }

    const float inw = 1.0f / 640.0f, inh = 1.0f / 400.0f;
    float c0x1 = r0[0]*inw, c0y1 = r0[1]*inh, c0x2 = r0[2]*inw, c0y2 = r0[3]*inh;
    float c1x1 = r1[0]*inw, c1y1 = r1[1]*inh, c1x2 = r1[2]*inw, c1y2 = r1[3]*inh;
    float s0 = c0x1 + c0y1 + c0x2 + c0y2;
    float s1 = c1x1 + c1y1 + c1x2 + c1y2;
    float pr0 = (s0 != 0.0f) ? 1.0f : 0.0f;
    float pr1 = (s1 != 0.0f) ? 1.0f : 0.0f;
    float k0 = r0[4] + (1.0f - pr0) * 1000.0f;
    float k1 = r1[4] + (1.0f - pr1) * 1000.0f;
    bool swp = (k1 < k0);
    bool takeSecond = swp ? (jj == 0) : (jj == 1);

    float x1 = takeSecond ? c1x1 : c0x1;
    float y1 = takeSecond ? c1y1 : c0y1;
    float x2 = takeSecond ? c1x2 : c0x2;
    float y2 = takeSecond ? c1y2 : c0y2;
    float cat = takeSecond ? r1[4] : r0[4];
    float cf  = takeSecond ? r1[5] : r0[5];
    float pr  = takeSecond ? pr1  : pr0;

    float w  = x2 - x1, hh = y2 - y1;
    float cx = (x1 + x2) * 0.5f, cy = (y1 + y2) * 0.5f;
    float area = w * hh;
    float asp  = w / (hh + 1e-6f);
    float ge[10] = {x1, y1, x2, y2, w, hh, cx, cy, area, asp};

    float pre[8];
#pragma unroll
    for (int i = 0; i < 8; i++) {
        int d = i * 32 + lane;
        float acc = __ldg(b1 + d);
#pragma unroll
        for (int k = 0; k < 10; k++) acc = fmaf(ge[k], __ldg(w1 + k * 256 + d), acc);
        pre[i] = acc;
    }
    float s = pre[0]+pre[1]+pre[2]+pre[3]+pre[4]+pre[5]+pre[6]+pre[7];
#pragma unroll
    for (int o = 16; o > 0; o >>= 1) s += __shfl_xor_sync(0xffffffffu, s, o);
    float mu = s * (1.0f / 256.0f);
    float v = 0.0f;
#pragma unroll
    for (int i = 0; i < 8; i++) { float d0 = pre[i] - mu; v = fmaf(d0, d0, v); }
#pragma unroll
    for (int o = 16; o > 0; o >>= 1) v += __shfl_xor_sync(0xffffffffu, v, o);
    float inv = rsqrtf(v * (1.0f / 256.0f) + 1e-5f);

    __nv_bfloat16* arow = g_A + (size_t)m * 512;
#pragma unroll
    for (int i = 0; i < 8; i++) {
        int d = i * 32 + lane;
        float x = (pre[i] - mu) * inv * __ldg(lng + d) + __ldg(lnb + d);
        float gl = 0.5f * x * (1.0f + erff(x * 0.70710678118654752440f));
        __nv_bfloat16 hi = __float2bfloat16(gl);
        float lo = gl - __bfloat162float(hi);
        arow[d]       = hi;
        arow[256 + d] = __float2bfloat16(lo);
    }

    if (lane == 0) {
        float pc = ((float)(int)cat) + ((pr == 0.0f) ? 8.0f : 0.0f);
        g_meta[m] = make_float4(pc, cf, cx, cy);
    }

    if (jj == 0) {
        float cxa = (c0x1 + c0x2) * 0.5f, cya = (c0y1 + c0y2) * 0.5f;
        float cxb = (c1x1 + c1x2) * 0.5f, cyb = (c1y1 + c1y2) * 0.5f;
        float dx = cxa - cxb, dy = cya - cyb;
        float dist = sqrtf(dx * dx + dy * dy);
        int b  = grp / GPB;
        int gg = grp - b * GPB;
        float* orow = out + ((size_t)b * RPB + gg) * 512;
#pragma unroll
        for (int i = 0; i < 16; i++) {
            int n = i * 32 + lane;
            orow[n] = fmaf(dist, __ldg(dw + n), __ldg(db + n));
        }
    }
}

// ============================================================
// Kernel W: split w2 into bf16 hi/hi/lo (K-major per n)
// ============================================================
__global__ void wprep_kernel(const float* __restrict__ w2)
{
    int n = blockIdx.x;      // 0..511
    int k = threadIdx.x;     // 0..255
    float x = __ldg(w2 + (size_t)k * 512 + n);
    __nv_bfloat16 hi = __float2bfloat16(x);
    float lo = x - __bfloat162float(hi);
    __nv_bfloat16* row = g_B + (size_t)n * 768;
    row[k]       = hi;
    row[256 + k] = hi;
    row[512 + k] = __float2bfloat16(lo);
}

// ============================================================
// Kernel E: epilogue tables. E[cat*3+cam][n], T4[n].
// ============================================================
__global__ void eprep_kernel(
    const float* __restrict__ b2,    const float* __restrict__ catT,
    const float* __restrict__ confw, const float* __restrict__ confb,
    const float* __restrict__ cw,    const float* __restrict__ cb,
    const float* __restrict__ miss,  const float* __restrict__ cam)
{
    int e = blockIdx.x;      // 0..9
    int n = threadIdx.x;     // 0..511
    if (e < 9) {
        int c = e / 3, v = e % 3;
        g_E[e * 512 + n] = __ldg(b2 + n) + __ldg(confb + n) + __ldg(cb + n)
                         + __ldg(catT + c * 512 + n) + __ldg(cam + v * 512 + n);
    } else {
        g_T4[n] = make_float4(__ldg(confw + n), __ldg(cw + n),
                              __ldg(cw + 512 + n), __ldg(miss + n));
    }
}

// ============================================================
// Kernel G: bf16 mma.sync GEMM [153600,768']x[768',512] (3-term
// split) + fused epilogue. BM=128, BN=128, BK=32, 8 warps,
// 4-stage cp.async pipeline, ONE __syncthreads per chunk.
// ============================================================
#define STAGES     4
#define TILE_ELEMS (128 * 40)            // one tile (padded)
#define TILE_BYTES (TILE_ELEMS * 2)      // 10240
#define SMEM_GEMM  (2 * STAGES * TILE_BYTES)   // 81920

__global__ void __launch_bounds__(256, 2) gemm_kernel(
    const float* __restrict__ scale_p, float* __restrict__ out)
{
    extern __shared__ __nv_bfloat16 smem_dyn[];
    uint32_t sbase = smem_u32(smem_dyn);
    uint32_t sbb   = sbase + STAGES * TILE_BYTES;   // B tiles base

    int tid = threadIdx.x;
    int m0 = blockIdx.x * 128, n0 = blockIdx.y * 128;
    int warp = tid >> 5, lane = tid & 31;
    int wm = warp >> 1, wn = warp & 1;

    // loader lanes: row = tid>>2 (0..63) and +64 ; k-col = (tid&3)*8
    int ldrow = tid >> 2, ldkc = (tid & 3) * 8;
    uint32_t aoff  = (uint32_t)(ldrow * 40 + ldkc) * 2;
    uint32_t aoff2 = (uint32_t)((ldrow + 64) * 40 + ldkc) * 2;

    float acc[2][8][4];
#pragma unroll
    for (int i = 0; i < 2; i++)
#pragma unroll
        for (int j = 0; j < 8; j++)
#pragma unroll
            for (int v = 0; v < 4; v++) acc[i][j][v] = 0.0f;

    // fragment smem coordinates
    int arow  = wm * 32 + (lane & 15);
    int acol8 = (lane >> 4) * 8;
    int brow  = wn * 64 + (lane & 7) + (lane >> 4) * 8;
    int bcol8 = ((lane >> 3) & 1) * 8;
    uint32_t a_base0 = sbase + (uint32_t)(arow * 40 + acol8) * 2;
    uint32_t a_base1 = sbase + (uint32_t)((arow + 16) * 40 + acol8) * 2;
    uint32_t b_base  = sbb   + (uint32_t)(brow * 40 + bcol8) * 2;

#define LOAD_STAGE(c, s) do {                                                    \
    int acol = ((c) < 16) ? (c) * 32 : (c) * 32 - 512;                           \
    const __nv_bfloat16* gA = g_A + (size_t)(m0 + ldrow) * 512 + acol + ldkc;    \
    const __nv_bfloat16* gB = g_B + (size_t)(n0 + ldrow) * 768 + (c) * 32 + ldkc;\
    uint32_t sA = sbase + (uint32_t)(s) * TILE_BYTES;                            \
    uint32_t sB = sbb   + (uint32_t)(s) * TILE_BYTES;                            \
    cpasync16(sA + aoff,  gA);                                                   \
    cpasync16(sA + aoff2, gA + (size_t)64 * 512);                                \
    cpasync16(sB + aoff,  gB);                                                   \
    cpasync16(sB + aoff2, gB + (size_t)64 * 768);                                \
    CP_COMMIT();                                                                 \
} while (0)

    LOAD_STAGE(0, 0);
    LOAD_STAGE(1, 1);
    LOAD_STAGE(2, 2);

#pragma unroll 4
    for (int c = 0; c < 24; c++) {
        int s = c & 3;
        if (c < 22)       CP_WAIT(2);
        else if (c == 22) CP_WAIT(1);
        else              CP_WAIT(0);
        __syncthreads();   // stage c ready; buffer (c+3)%4's old consumer (iter c-1) done

        if (c + 3 < 24) LOAD_STAGE(c + 3, (c + 3) & 3);

        uint32_t soff = (uint32_t)s * TILE_BYTES;
#pragma unroll
        for (int ks = 0; ks < 2; ks++) {
            uint32_t a[2][4], b[4][4];
            uint32_t kb = soff + ks * 32;    // 16 bf16 = 32 bytes
            ldm_x4(a[0], a_base0 + kb);
            ldm_x4(a[1], a_base1 + kb);
#pragma unroll
            for (int jp = 0; jp < 4; jp++)
                ldm_x4(b[jp], b_base + kb + (uint32_t)(jp * 16 * 40) * 2);
#pragma unroll
            for (int ti = 0; ti < 2; ti++)
#pragma unroll
                for (int jp = 0; jp < 4; jp++) {
                    mma16816(acc[ti][jp * 2],     a[ti], b[jp][0], b[jp][1]);
                    mma16816(acc[ti][jp * 2 + 1], a[ti], b[jp][2], b[jp][3]);
                }
        }
    }
#undef LOAD_STAGE

    // ---------------- epilogue ----------------
    float scl = __ldg(scale_p);
    int lane4 = lane >> 2;
    int colp  = (lane & 3) * 2;

#pragma unroll
    for (int ti = 0; ti < 2; ti++) {
        int mA = m0 + wm * 32 + ti * 16 + lane4;
        int mB = mA + 8;
        float4 mtA = g_meta[mA];
        float4 mtB = g_meta[mB];
        int pcA = (int)mtA.x, pcB = (int)mtB.x;
        const float* eA = g_E + (size_t)((pcA & 3) * 3 + ((mA >> 1) % 3)) * 512;
        const float* eB = g_E + (size_t)((pcB & 3) * 3 + ((mB >> 1) % 3)) * 512;
        bool msA = (pcA >= 8), msB = (pcB >= 8);
        int bA = mA / 1200, rA = mA - bA * 1200;
        int bB = mB / 1200, rB = mB - bB * 1200;
        float* oA = out + ((size_t)bA * RPB + 600 + rA) * 512;
        float* oB = out + ((size_t)bB * RPB + 600 + rB) * 512;

#pragma unroll
        for (int j = 0; j < 8; j++) {
            int n = n0 + wn * 64 + j * 8 + colp;
            float4 t0 = g_T4[n], t1 = g_T4[n + 1];
            float v0 = (acc[ti][j][0] + eA[n]     + mtA.y * t0.x + mtA.z * t0.y + mtA.w * t0.z) * scl;
            float v1 = (acc[ti][j][1] + eA[n + 1] + mtA.y * t1.x + mtA.z * t1.y + mtA.w * t1.z) * scl;
            if (msA) { v0 = t0.w; v1 = t1.w; }
            *(float2*)(oA + n) = make_float2(v0, v1);

            float u0 = (acc[ti][j][2] + eB[n]     + mtB.y * t0.x + mtB.z * t0.y + mtB.w * t0.z) * scl;
            float u1 = (acc[ti][j][3] + eB[n + 1] + mtB.y * t1.x + mtB.z * t1.y + mtB.w * t1.z) * scl;
            if (msB) { u0 = t0.w; u1 = t1.w; }
            *(float2*)(oB + n) = make_float2(u0, u1);
        }
    }
}

// ============================================================
extern "C" void kernel_launch(void* const* d_in, const int* in_sizes, int n_in,
                              void* d_out, int out_size)
{
    const float* box   = (const float*)d_in[0];
    const float* catT  = (const float*)d_in[1];
    const float* w1    = (const float*)d_in[2];
    const float* b1    = (const float*)d_in[3];
    const float* lng   = (const float*)d_in[4];
    const float* lnb   = (const float*)d_in[5];
    const float* w2    = (const float*)d_in[6];
    const float* b2    = (const float*)d_in[7];
    const float* confw = (const float*)d_in[8];
    const float* confb = (const float*)d_in[9];
    const float* cw    = (const float*)d_in[10];
    const float* cb    = (const float*)d_in[11];
    const float* miss  = (const float*)d_in[12];
    const float* dw    = (const float*)d_in[13];
    const float* db    = (const float*)d_in[14];
    const float* cam   = (const float*)d_in[15];
    const float* scale = (const float*)d_in[16];
    float* out = (float*)d_out;

    cudaFuncSetAttribute(gemm_kernel, cudaFuncAttributeMaxDynamicSharedMemorySize, SMEM_GEMM);

    wprep_kernel<<<512, 256>>>(w2);
    eprep_kernel<<<10, 512>>>(b2, catT, confw, confb, cw, cb, miss, cam);
    prep_kernel<<<NBOXES / 8, 256>>>(box, w1, b1, lng, lnb, dw, db, out);

    dim3 grid(NBOXES / 128, 4);   // 1200 x 4
    gemm_kernel<<<grid, 256, SMEM_GEMM>>>(scale, out);
}

// round 5
// speedup vs baseline: 2.4204x; 1.2776x over previous
#include <cuda_runtime.h>
#include <cuda_fp16.h>
#include <math.h>
#include <stdint.h>

// Problem constants: B=128, T=200, NC=3, NB=2, D=512, DH=256
#define NBOXES  153600
#define GPB     600
#define RPB     1800

// ---------------- scratch ----------------
// A2[m][0:256) = fp16(a), [256:512) = fp16(a * 2^-6)
__device__ __half  g_A[(size_t)NBOXES * 512];
// B2[n][0:256) = fp16(b), [256:512) = fp16((b - fp16(b)) * 2^6)
__device__ __half  g_B[512 * 512];
__device__ float4  g_meta[NBOXES];   // {catI + 8*(missing), conf, cx, cy}
__device__ float   g_E[9 * 512];     // b2+confb+cb+catT[c]+cam[v]
__device__ float4  g_T4[512];        // {confw, cw0, cw1, miss}

// ---------------- helpers ----------------
__device__ __forceinline__ uint32_t smem_u32(const void* p) {
    uint32_t a;
    asm("{ .reg .u64 t; cvta.to.shared.u64 t, %1; cvt.u32.u64 %0, t; }" : "=r"(a) : "l"(p));
    return a;
}
__device__ __forceinline__ void cpasync16(uint32_t s, const void* g) {
    asm volatile("cp.async.cg.shared.global [%0], [%1], 16;" :: "r"(s), "l"(g));
}
#define CP_COMMIT() asm volatile("cp.async.commit_group;" ::: "memory")
#define CP_WAIT(n)  asm volatile("cp.async.wait_group %0;" :: "n"(n) : "memory")

__device__ __forceinline__ void ldm_x4(uint32_t* r, uint32_t addr) {
    asm volatile("ldmatrix.sync.aligned.m8n8.x4.shared.b16 {%0,%1,%2,%3}, [%4];"
        : "=r"(r[0]), "=r"(r[1]), "=r"(r[2]), "=r"(r[3]) : "r"(addr));
}
__device__ __forceinline__ void mma16816(float* d, const uint32_t* a, uint32_t b0, uint32_t b1) {
    asm volatile(
        "mma.sync.aligned.m16n8k16.row.col.f32.f16.f16.f32 "
        "{%0,%1,%2,%3}, {%4,%5,%6,%7}, {%8,%9}, {%0,%1,%2,%3};"
        : "+f"(d[0]), "+f"(d[1]), "+f"(d[2]), "+f"(d[3])
        : "r"(a[0]), "r"(a[1]), "r"(a[2]), "r"(a[3]), "r"(b0), "r"(b1));
}

// ============================================================
// Kernel A: per-box prep (one warp per box).
// ============================================================
__global__ void __launch_bounds__(256) prep_kernel(
    const float* __restrict__ box,
    const float* __restrict__ w1,  const float* __restrict__ b1,
    const float* __restrict__ lng, const float* __restrict__ lnb,
    const float* __restrict__ dw,  const float* __restrict__ db,
    float* __restrict__ out)
{
    int m    = blockIdx.x * 8 + (threadIdx.x >> 5);
    int lane = threadIdx.x & 31;
    int grp  = m >> 1;
    int jj   = m & 1;

    const float* p = box + (size_t)grp * 12;
    float r0[6], r1[6];
#pragma unroll
    for (int i = 0; i < 6; i++) { r0[i] = __ldg(p + i); r1[i] = __ldg(p + 6 + i); }

    const float inw = 1.0f / 640.0f, inh = 1.0f / 400.0f;
    float c0x1 = r0[0]*inw, c0y1 = r0[1]*inh, c0x2 = r0[2]*inw, c0y2 = r0[3]*inh;
    float c1x1 = r1[0]*inw, c1y1 = r1[1]*inh, c1x2 = r1[2]*inw, c1y2 = r1[3]*inh;
    float s0 = c0x1 + c0y1 + c0x2 + c0y2;
    float s1 = c1x1 + c1y1 + c1x2 + c1y2;
    float pr0 = (s0 != 0.0f) ? 1.0f : 0.0f;
    float pr1 = (s1 != 0.0f) ? 1.0f : 0.0f;
    float k0 = r0[4] + (1.0f - pr0) * 1000.0f;
    float k1 = r1[4] + (1.0f - pr1) * 1000.0f;
    bool swp = (k1 < k0);
    bool takeSecond = swp ? (jj == 0) : (jj == 1);

    float x1 = takeSecond ? c1x1 : c0x1;
    float y1 = takeSecond ? c1y1 : c0y1;
    float x2 = takeSecond ? c1x2 : c0x2;
    float y2 = takeSecond ? c1y2 : c0y2;
    float cat = takeSecond ? r1[4] : r0[4];
    float cf  = takeSecond ? r1[5] : r0[5];
    float pr  = takeSecond ? pr1  : pr0;

    float w  = x2 - x1, hh = y2 - y1;
    float cx = (x1 + x2) * 0.5f, cy = (y1 + y2) * 0.5f;
    float area = w * hh;
    float asp  = w / (hh + 1e-6f);
    float ge[10] = {x1, y1, x2, y2, w, hh, cx, cy, area, asp};

    float pre[8];
#pragma unroll
    for (int i = 0; i < 8; i++) {
        int d = i * 32 + lane;
        float acc = __ldg(b1 + d);
#pragma unroll
        for (int k = 0; k < 10; k++) acc = fmaf(ge[k], __ldg(w1 + k * 256 + d), acc);
        pre[i] = acc;
    }
    float s = pre[0]+pre[1]+pre[2]+pre[3]+pre[4]+pre[5]+pre[6]+pre[7];
#pragma unroll
    for (int o = 16; o > 0; o >>= 1) s += __shfl_xor_sync(0xffffffffu, s, o);
    float mu = s * (1.0f / 256.0f);
    float v = 0.0f;
#pragma unroll
    for (int i = 0; i < 8; i++) { float d0 = pre[i] - mu; v = fmaf(d0, d0, v); }
#pragma unroll
    for (int o = 16; o > 0; o >>= 1) v += __shfl_xor_sync(0xffffffffu, v, o);
    float inv = rsqrtf(v * (1.0f / 256.0f) + 1e-5f);

    __half* arow = g_A + (size_t)m * 512;
#pragma unroll
    for (int i = 0; i < 8; i++) {
        int d = i * 32 + lane;
        float x = (pre[i] - mu) * inv * __ldg(lng + d) + __ldg(lnb + d);
        float gl = 0.5f * x * (1.0f + erff(x * 0.70710678118654752440f));
        arow[d]       = __float2half(gl);
        arow[256 + d] = __float2half(gl * 0.015625f);   // a * 2^-6
    }

    if (lane == 0) {
        float pc = ((float)(int)cat) + ((pr == 0.0f) ? 8.0f : 0.0f);
        g_meta[m] = make_float4(pc, cf, cx, cy);
    }

    if (jj == 0) {
        float cxa = (c0x1 + c0x2) * 0.5f, cya = (c0y1 + c0y2) * 0.5f;
        float cxb = (c1x1 + c1x2) * 0.5f, cyb = (c1y1 + c1y2) * 0.5f;
        float dx = cxa - cxb, dy = cya - cyb;
        float dist = sqrtf(dx * dx + dy * dy);
        int b  = grp / GPB;
        int gg = grp - b * GPB;
        float* orow = out + ((size_t)b * RPB + gg) * 512;
#pragma unroll
        for (int i = 0; i < 16; i++) {
            int n = i * 32 + lane;
            orow[n] = fmaf(dist, __ldg(dw + n), __ldg(db + n));
        }
    }
}

// ============================================================
// Kernel W: split w2 into fp16 hi + scaled residual (K-major)
// ============================================================
__global__ void wprep_kernel(const float* __restrict__ w2)
{
    int n = blockIdx.x;      // 0..511
    int k = threadIdx.x;     // 0..255
    float x = __ldg(w2 + (size_t)k * 512 + n);
    __half h = __float2half(x);
    float lo = (x - __half2float(h)) * 64.0f;   // * 2^6
    __half* row = g_B + (size_t)n * 512;
    row[k]       = h;
    row[256 + k] = __float2half(lo);
}

// ============================================================
// Kernel E: epilogue tables. E[cat*3+cam][n], T4[n].
// ============================================================
__global__ void eprep_kernel(
    const float* __restrict__ b2,    const float* __restrict__ catT,
    const float* __restrict__ confw, const float* __restrict__ confb,
    const float* __restrict__ cw,    const float* __restrict__ cb,
    const float* __restrict__ miss,  const float* __restrict__ cam)
{
    int e = blockIdx.x;      // 0..9
    int n = threadIdx.x;     // 0..511
    if (e < 9) {
        int c = e / 3, v = e % 3;
        g_E[e * 512 + n] = __ldg(b2 + n) + __ldg(confb + n) + __ldg(cb + n)
                         + __ldg(catT + c * 512 + n) + __ldg(cam + v * 512 + n);
    } else {
        g_T4[n] = make_float4(__ldg(confw + n), __ldg(cw + n),
                              __ldg(cw + 512 + n), __ldg(miss + n));
    }
}

// ============================================================
// Kernel G: fp16 mma.sync GEMM [153600,512']x[512',512] (2-term
// split) + fused epilogue. BM=128, BN=128, BK=32, 8 warps,
// 4-stage cp.async pipeline. Grid: n fastest (A reuse in L2).
// ============================================================
#define STAGES     4
#define TILE_ELEMS (128 * 40)            // one tile (padded)
#define TILE_BYTES (TILE_ELEMS * 2)      // 10240
#define SMEM_GEMM  (2 * STAGES * TILE_BYTES)   // 81920
#define NCHUNKS    16                    // K' = 512 / 32

__global__ void __launch_bounds__(256, 2) gemm_kernel(
    const float* __restrict__ scale_p, float* __restrict__ out)
{
    extern __shared__ __half smem_dyn[];
    uint32_t sbase = smem_u32(smem_dyn);
    uint32_t sbb   = sbase + STAGES * TILE_BYTES;   // B tiles base

    int tid = threadIdx.x;
    int n0 = blockIdx.x * 128, m0 = blockIdx.y * 128;   // n fastest!
    int warp = tid >> 5, lane = tid & 31;
    int wm = warp >> 1, wn = warp & 1;

    int ldrow = tid >> 2, ldkc = (tid & 3) * 8;
    uint32_t aoff  = (uint32_t)(ldrow * 40 + ldkc) * 2;
    uint32_t aoff2 = (uint32_t)((ldrow + 64) * 40 + ldkc) * 2;

    float acc[2][8][4];
#pragma unroll
    for (int i = 0; i < 2; i++)
#pragma unroll
        for (int j = 0; j < 8; j++)
#pragma unroll
            for (int v = 0; v < 4; v++) acc[i][j][v] = 0.0f;

    int arow  = wm * 32 + (lane & 15);
    int acol8 = (lane >> 4) * 8;
    int brow  = wn * 64 + (lane & 7) + (lane >> 4) * 8;
    int bcol8 = ((lane >> 3) & 1) * 8;
    uint32_t a_base0 = sbase + (uint32_t)(arow * 40 + acol8) * 2;
    uint32_t a_base1 = sbase + (uint32_t)((arow + 16) * 40 + acol8) * 2;
    uint32_t b_base  = sbb   + (uint32_t)(brow * 40 + bcol8) * 2;

#define LOAD_STAGE(c, s) do {                                                    \
    const __half* gA = g_A + (size_t)(m0 + ldrow) * 512 + (c) * 32 + ldkc;       \
    const __half* gB = g_B + (size_t)(n0 + ldrow) * 512 + (c) * 32 + ldkc;       \
    uint32_t sA = sbase + (uint32_t)(s) * TILE_BYTES;                            \
    uint32_t sB = sbb   + (uint32_t)(s) * TILE_BYTES;                            \
    cpasync16(sA + aoff,  gA);                                                   \
    cpasync16(sA + aoff2, gA + (size_t)64 * 512);                                \
    cpasync16(sB + aoff,  gB);                                                   \
    cpasync16(sB + aoff2, gB + (size_t)64 * 512);                                \
    CP_COMMIT();                                                                 \
} while (0)

    LOAD_STAGE(0, 0);
    LOAD_STAGE(1, 1);
    LOAD_STAGE(2, 2);

#pragma unroll 4
    for (int c = 0; c < NCHUNKS; c++) {
        int s = c & 3;
        if (c < NCHUNKS - 2)       CP_WAIT(2);
        else if (c == NCHUNKS - 2) CP_WAIT(1);
        else                       CP_WAIT(0);
        __syncthreads();

        if (c + 3 < NCHUNKS) LOAD_STAGE(c + 3, (c + 3) & 3);

        uint32_t soff = (uint32_t)s * TILE_BYTES;
#pragma unroll
        for (int ks = 0; ks < 2; ks++) {
            uint32_t a[2][4], b[4][4];
            uint32_t kb = soff + ks * 32;
            ldm_x4(a[0], a_base0 + kb);
            ldm_x4(a[1], a_base1 + kb);
#pragma unroll
            for (int jp = 0; jp < 4; jp++)
                ldm_x4(b[jp], b_base + kb + (uint32_t)(jp * 16 * 40) * 2);
#pragma unroll
            for (int ti = 0; ti < 2; ti++)
#pragma unroll
                for (int jp = 0; jp < 4; jp++) {
                    mma16816(acc[ti][jp * 2],     a[ti], b[jp][0], b[jp][1]);
                    mma16816(acc[ti][jp * 2 + 1], a[ti], b[jp][2], b[jp][3]);
                }
        }
    }
#undef LOAD_STAGE

    // ---------------- epilogue ----------------
    float scl = __ldg(scale_p);
    int lane4 = lane >> 2;
    int colp  = (lane & 3) * 2;

#pragma unroll
    for (int ti = 0; ti < 2; ti++) {
        int mA = m0 + wm * 32 + ti * 16 + lane4;
        int mB = mA + 8;
        float4 mtA = g_meta[mA];
        float4 mtB = g_meta[mB];
        int pcA = (int)mtA.x, pcB = (int)mtB.x;
        const float* eA = g_E + (size_t)((pcA & 3) * 3 + ((mA >> 1) % 3)) * 512;
        const float* eB = g_E + (size_t)((pcB & 3) * 3 + ((mB >> 1) % 3)) * 512;
        bool msA = (pcA >= 8), msB = (pcB >= 8);
        int bA = mA / 1200, rA = mA - bA * 1200;
        int bB = mB / 1200, rB = mB - bB * 1200;
        float* oA = out + ((size_t)bA * RPB + 600 + rA) * 512;
        float* oB = out + ((size_t)bB * RPB + 600 + rB) * 512;

#pragma unroll
        for (int j = 0; j < 8; j++) {
            int n = n0 + wn * 64 + j * 8 + colp;
            float4 t0 = g_T4[n], t1 = g_T4[n + 1];
            float v0 = (acc[ti][j][0] + eA[n]     + mtA.y * t0.x + mtA.z * t0.y + mtA.w * t0.z) * scl;
            float v1 = (acc[ti][j][1] + eA[n + 1] + mtA.y * t1.x + mtA.z * t1.y + mtA.w * t1.z) * scl;
            if (msA) { v0 = t0.w; v1 = t1.w; }
            *(float2*)(oA + n) = make_float2(v0, v1);

            float u0 = (acc[ti][j][2] + eB[n]     + mtB.y * t0.x + mtB.z * t0.y + mtB.w * t0.z) * scl;
            float u1 = (acc[ti][j][3] + eB[n + 1] + mtB.y * t1.x + mtB.z * t1.y + mtB.w * t1.z) * scl;
            if (msB) { u0 = t0.w; u1 = t1.w; }
            *(float2*)(oB + n) = make_float2(u0, u1);
        }
    }
}

// ============================================================
extern "C" void kernel_launch(void* const* d_in, const int* in_sizes, int n_in,
                              void* d_out, int out_size)
{
    const float* box   = (const float*)d_in[0];
    const float* catT  = (const float*)d_in[1];
    const float* w1    = (const float*)d_in[2];
    const float* b1    = (const float*)d_in[3];
    const float* lng   = (const float*)d_in[4];
    const float* lnb   = (const float*)d_in[5];
    const float* w2    = (const float*)d_in[6];
    const float* b2    = (const float*)d_in[7];
    const float* confw = (const float*)d_in[8];
    const float* confb = (const float*)d_in[9];
    const float* cw    = (const float*)d_in[10];
    const float* cb    = (const float*)d_in[11];
    const float* miss  = (const float*)d_in[12];
    const float* dw    = (const float*)d_in[13];
    const float* db    = (const float*)d_in[14];
    const float* cam   = (const float*)d_in[15];
    const float* scale = (const float*)d_in[16];
    float* out = (float*)d_out;

    cudaFuncSetAttribute(gemm_kernel, cudaFuncAttributeMaxDynamicSharedMemorySize, SMEM_GEMM);

    wprep_kernel<<<512, 256>>>(w2);
    eprep_kernel<<<10, 512>>>(b2, catT, confw, confb, cw, cb, miss, cam);
    prep_kernel<<<NBOXES / 8, 256>>>(box, w1, b1, lng, lnb, dw, db, out);

    dim3 grid(4, NBOXES / 128);   // n fastest: 4 x 1200
    gemm_kernel<<<grid, 256, SMEM_GEMM>>>(scale, out);
}

// round 7
// speedup vs baseline: 2.8703x; 1.1859x over previous
#include <cuda_runtime.h>
#include <cuda_fp16.h>
#include <math.h>
#include <stdint.h>

// Problem constants: B=128, T=200, NC=3, NB=2, D=512, DH=256
#define NBOXES  153600
#define GPB     600
#define RPB     1800

// ---------------- scratch ----------------
// Compacted A (present boxes only): [slot][0:256)=fp16(a), [256:512)=fp16(a*2^-6)
__device__ __half  g_A[(size_t)NBOXES * 512];
// B2[n][0:256) = fp16(b), [256:512) = fp16((b - fp16(b)) * 2^6)
__device__ __half  g_B[512 * 512];
__device__ float4  g_meta[NBOXES];   // per slot: {float(m*4+cat), conf, cx, cy}
__device__ float   g_E[9 * 512];     // b2+confb+cb+catT[c]+cam[v]
__device__ float4  g_T4[512];        // {confw, cw0, cw1, miss}
__device__ int     g_cnt;            // number of present boxes (compacted rows)

// ---------------- helpers ----------------
__device__ __forceinline__ uint32_t smem_u32(const void* p) {
    uint32_t a;
    asm("{ .reg .u64 t; cvta.to.shared.u64 t, %1; cvt.u32.u64 %0, t; }" : "=r"(a) : "l"(p));
    return a;
}
__device__ __forceinline__ void cpasync16(uint32_t s, const void* g) {
    asm volatile("cp.async.cg.shared.global [%0], [%1], 16;" :: "r"(s), "l"(g));
}
#define CP_COMMIT() asm volatile("cp.async.commit_group;" ::: "memory")
#define CP_WAIT(n)  asm volatile("cp.async.wait_group %0;" :: "n"(n) : "memory")

__device__ __forceinline__ void ldm_x4(uint32_t* r, uint32_t addr) {
    asm volatile("ldmatrix.sync.aligned.m8n8.x4.shared.b16 {%0,%1,%2,%3}, [%4];"
        : "=r"(r[0]), "=r"(r[1]), "=r"(r[2]), "=r"(r[3]) : "r"(addr));
}
__device__ __forceinline__ void mma16816(float* d, const uint32_t* a, uint32_t b0, uint32_t b1) {
    asm volatile(
        "mma.sync.aligned.m16n8k16.row.col.f32.f16.f16.f32 "
        "{%0,%1,%2,%3}, {%4,%5,%6,%7}, {%8,%9}, {%0,%1,%2,%3};"
        : "+f"(d[0]), "+f"(d[1]), "+f"(d[2]), "+f"(d[3])
        : "r"(a[0]), "r"(a[1]), "r"(a[2]), "r"(a[3]), "r"(b0), "r"(b1));
}

// ============================================================
// Kernel AUX: w2 split (blocks 0..511), epilogue tables
// (blocks 512..521), counter reset (block 522). 512 threads.
// ============================================================
__global__ void aux_kernel(
    const float* __restrict__ w2,
    const float* __restrict__ b2,    const float* __restrict__ catT,
    const float* __restrict__ confw, const float* __restrict__ confb,
    const float* __restrict__ cw,    const float* __restrict__ cb,
    const float* __restrict__ miss,  const float* __restrict__ cam)
{
    int blk = blockIdx.x;
    int t = threadIdx.x;
    if (blk < 512) {
        if (t < 256) {
            int n = blk, k = t;
            float x = __ldg(w2 + (size_t)k * 512 + n);
            __half h = __float2half(x);
            float lo = (x - __half2float(h)) * 64.0f;   // * 2^6
            __half* row = g_B + (size_t)n * 512;
            row[k]       = h;
            row[256 + k] = __float2half(lo);
        }
    } else if (blk < 521) {
        int e = blk - 512;
        int n = t;
        int c = e / 3, v = e % 3;
        g_E[e * 512 + n] = __ldg(b2 + n) + __ldg(confb + n) + __ldg(cb + n)
                         + __ldg(catT + c * 512 + n) + __ldg(cam + v * 512 + n);
    } else if (blk == 521) {
        int n = t;
        g_T4[n] = make_float4(__ldg(confw + n), __ldg(cw + n),
                              __ldg(cw + 512 + n), __ldg(miss + n));
    } else {
        if (t == 0) g_cnt = 0;
    }
}

// ============================================================
// Kernel A: per-box prep (one warp per box), compaction of
// present boxes into g_A, direct missing_emb writes to out.
// ============================================================
__global__ void __launch_bounds__(256) prep_kernel(
    const float* __restrict__ box,
    const float* __restrict__ w1,  const float* __restrict__ b1,
    const float* __restrict__ lng, const float* __restrict__ lnb,
    const float* __restrict__ dw,  const float* __restrict__ db,
    const float* __restrict__ missv,
    float* __restrict__ out)
{
    __shared__ int s_pref[8];
    __shared__ int s_base;

    int wid  = threadIdx.x >> 5;
    int m    = blockIdx.x * 8 + wid;
    int lane = threadIdx.x & 31;
    int grp  = m >> 1;
    int jj   = m & 1;

    const float* p = box + (size_t)grp * 12;
    float r0[6], r1[6];
#pragma unroll
    for (int i = 0; i < 6; i++) { r0[i] = __ldg(p + i); r1[i] = __ldg(p + 6 + i); }

    const float inw = 1.0f / 640.0f, inh = 1.0f / 400.0f;
    float c0x1 = r0[0]*inw, c0y1 = r0[1]*inh, c0x2 = r0[2]*inw, c0y2 = r0[3]*inh;
    float c1x1 = r1[0]*inw, c1y1 = r1[1]*inh, c1x2 = r1[2]*inw, c1y2 = r1[3]*inh;
    float s0 = c0x1 + c0y1 + c0x2 + c0y2;
    float s1 = c1x1 + c1y1 + c1x2 + c1y2;
    float pr0 = (s0 != 0.0f) ? 1.0f : 0.0f;
    float pr1 = (s1 != 0.0f) ? 1.0f : 0.0f;
    float k0 = r0[4] + (1.0f - pr0) * 1000.0f;
    float k1 = r1[4] + (1.0f - pr1) * 1000.0f;
    bool swp = (k1 < k0);
    bool takeSecond = swp ? (jj == 0) : (jj == 1);

    float x1 = takeSecond ? c1x1 : c0x1;
    float y1 = takeSecond ? c1y1 : c0y1;
    float x2 = takeSecond ? c1x2 : c0x2;
    float y2 = takeSecond ? c1y2 : c0y2;
    float cat = takeSecond ? r1[4] : r0[4];
    float cf  = takeSecond ? r1[5] : r0[5];
    float pr  = takeSecond ? pr1  : pr0;
    bool present = (pr != 0.0f);

    // block-aggregated slot assignment (one atomic per block)
    if (lane == 0) s_pref[wid] = present ? 1 : 0;
    __syncthreads();
    if (threadIdx.x == 0) {
        int run = 0;
#pragma unroll
        for (int i = 0; i < 8; i++) { int v = s_pref[i]; s_pref[i] = run; run += v; }
        s_base = atomicAdd(&g_cnt, run);
    }
    __syncthreads();
    int slot = s_base + s_pref[wid];

    // output row base for this box
    int bI = m / 1200;
    int rI = m - bI * 1200;
    float* orow = out + ((size_t)bI * RPB + 600 + rI) * 512;

    if (present) {
        float w  = x2 - x1, hh = y2 - y1;
        float cx = (x1 + x2) * 0.5f, cy = (y1 + y2) * 0.5f;
        float area = w * hh;
        float asp  = w / (hh + 1e-6f);
        float ge[10] = {x1, y1, x2, y2, w, hh, cx, cy, area, asp};

        // lane handles dims d0..d0+3 for i in {0,1}: d0 = i*128 + lane*4
        float pre[8];
#pragma unroll
        for (int i = 0; i < 2; i++) {
            int d0 = i * 128 + lane * 4;
            float4 acc = *(const float4*)(b1 + d0);
#pragma unroll
            for (int k = 0; k < 10; k++) {
                float4 wv = __ldg((const float4*)(w1 + k * 256 + d0));
                acc.x = fmaf(ge[k], wv.x, acc.x);
                acc.y = fmaf(ge[k], wv.y, acc.y);
                acc.z = fmaf(ge[k], wv.z, acc.z);
                acc.w = fmaf(ge[k], wv.w, acc.w);
            }
            pre[i*4+0] = acc.x; pre[i*4+1] = acc.y;
            pre[i*4+2] = acc.z; pre[i*4+3] = acc.w;
        }
        float s = pre[0]+pre[1]+pre[2]+pre[3]+pre[4]+pre[5]+pre[6]+pre[7];
#pragma unroll
        for (int o = 16; o > 0; o >>= 1) s += __shfl_xor_sync(0xffffffffu, s, o);
        float mu = s * (1.0f / 256.0f);
        float v = 0.0f;
#pragma unroll
        for (int i = 0; i < 8; i++) { float d0 = pre[i] - mu; v = fmaf(d0, d0, v); }
#pragma unroll
        for (int o = 16; o > 0; o >>= 1) v += __shfl_xor_sync(0xffffffffu, v, o);
        float inv = rsqrtf(v * (1.0f / 256.0f) + 1e-5f);

        __half* arow = g_A + (size_t)slot * 512;
#pragma unroll
        for (int i = 0; i < 2; i++) {
            int d0 = i * 128 + lane * 4;
            float4 gv = *(const float4*)(lng + d0);
            float4 bv = *(const float4*)(lnb + d0);
            float gl[4];
#pragma unroll
            for (int j = 0; j < 4; j++) {
                float gg = (j==0)?gv.x:((j==1)?gv.y:((j==2)?gv.z:gv.w));
                float bb = (j==0)?bv.x:((j==1)?bv.y:((j==2)?bv.z:bv.w));
                float x = (pre[i*4+j] - mu) * inv * gg + bb;
                gl[j] = 0.5f * x * (1.0f + erff(x * 0.70710678118654752440f));
            }
            __half2 h01 = __floats2half2_rn(gl[0], gl[1]);
            __half2 h23 = __floats2half2_rn(gl[2], gl[3]);
            __half2 l01 = __floats2half2_rn(gl[0]*0.015625f, gl[1]*0.015625f);
            __half2 l23 = __floats2half2_rn(gl[2]*0.015625f, gl[3]*0.015625f);
            *(uint2*)(arow + d0)       = make_uint2(*(uint32_t*)&h01, *(uint32_t*)&h23);
            *(uint2*)(arow + 256 + d0) = make_uint2(*(uint32_t*)&l01, *(uint32_t*)&l23);
        }

        if (lane == 0) {
            g_meta[slot] = make_float4((float)(m * 4 + (int)cat), cf, cx, cy);
        }
    } else {
        // missing: write missing_emb row directly (unscaled, per reference)
#pragma unroll
        for (int i = 0; i < 4; i++) {
            int n = i * 128 + lane * 4;
            *(float4*)(orow + n) = __ldg((const float4*)(missv + n));
        }
    }

    // dist token row (one per group; invariant to the pair swap)
    if (jj == 0) {
        float cxa = (c0x1 + c0x2) * 0.5f, cya = (c0y1 + c0y2) * 0.5f;
        float cxb = (c1x1 + c1x2) * 0.5f, cyb = (c1y1 + c1y2) * 0.5f;
        float dx = cxa - cxb, dy = cya - cyb;
        float dist = sqrtf(dx * dx + dy * dy);
        float* drow = out + ((size_t)bI * RPB + (grp - bI * GPB)) * 512;
#pragma unroll
        for (int i = 0; i < 4; i++) {
            int n = i * 128 + lane * 4;
            float4 wv = __ldg((const float4*)(dw + n));
            float4 bv = __ldg((const float4*)(db + n));
            *(float4*)(drow + n) = make_float4(fmaf(dist, wv.x, bv.x), fmaf(dist, wv.y, bv.y),
                                               fmaf(dist, wv.z, bv.z), fmaf(dist, wv.w, bv.w));
        }
    }
}

// ============================================================
// Kernel G: fp16 mma.sync GEMM on compacted rows + epilogue.
// BM=128, BN=128, BK=32, 8 warps, 4-stage cp.async pipeline.
// Fixed grid; blocks beyond compacted count early-exit.
// ============================================================
#define STAGES     4
#define TILE_ELEMS (128 * 40)
#define TILE_BYTES (TILE_ELEMS * 2)            // 10240
#define SMEM_GEMM  (2 * STAGES * TILE_BYTES)   // 81920
#define NCHUNKS    16

__global__ void __launch_bounds__(256, 2) gemm_kernel(
    const float* __restrict__ scale_p, float* __restrict__ out)
{
    int count = g_cnt;
    int m0 = blockIdx.y * 128;
    if (m0 >= count) return;

    extern __shared__ __half smem_dyn[];
    uint32_t sbase = smem_u32(smem_dyn);
    uint32_t sbb   = sbase + STAGES * TILE_BYTES;

    int tid = threadIdx.x;
    int n0 = blockIdx.x * 128;
    int warp = tid >> 5, lane = tid & 31;
    int wm = warp >> 1, wn = warp & 1;

    int ldrow = tid >> 2, ldkc = (tid & 3) * 8;
    uint32_t aoff  = (uint32_t)(ldrow * 40 + ldkc) * 2;
    uint32_t aoff2 = (uint32_t)((ldrow + 64) * 40 + ldkc) * 2;

    float acc[2][8][4];
#pragma unroll
    for (int i = 0; i < 2; i++)
#pragma unroll
        for (int j = 0; j < 8; j++)
#pragma unroll
            for (int v = 0; v < 4; v++) acc[i][j][v] = 0.0f;

    int arow  = wm * 32 + (lane & 15);
    int acol8 = (lane >> 4) * 8;
    int brow  = wn * 64 + (lane & 7) + (lane >> 4) * 8;
    int bcol8 = ((lane >> 3) & 1) * 8;
    uint32_t a_base0 = sbase + (uint32_t)(arow * 40 + acol8) * 2;
    uint32_t a_base1 = sbase + (uint32_t)((arow + 16) * 40 + acol8) * 2;
    uint32_t b_base  = sbb   + (uint32_t)(brow * 40 + bcol8) * 2;

#define LOAD_STAGE(c, s) do {                                                    \
    const __half* gA = g_A + (size_t)(m0 + ldrow) * 512 + (c) * 32 + ldkc;       \
    const __half* gB = g_B + (size_t)(n0 + ldrow) * 512 + (c) * 32 + ldkc;       \
    uint32_t sA = sbase + (uint32_t)(s) * TILE_BYTES;                            \
    uint32_t sB = sbb   + (uint32_t)(s) * TILE_BYTES;                            \
    cpasync16(sA + aoff,  gA);                                                   \
    cpasync16(sA + aoff2, gA + (size_t)64 * 512);                                \
    cpasync16(sB + aoff,  gB);                                                   \
    cpasync16(sB + aoff2, gB + (size_t)64 * 512);                                \
    CP_COMMIT();                                                                 \
} while (0)

    LOAD_STAGE(0, 0);
    LOAD_STAGE(1, 1);
    LOAD_STAGE(2, 2);

#pragma unroll 4
    for (int c = 0; c < NCHUNKS; c++) {
        int s = c & 3;
        if (c < NCHUNKS - 2)       CP_WAIT(2);
        else if (c == NCHUNKS - 2) CP_WAIT(1);
        else                       CP_WAIT(0);
        __syncthreads();

        if (c + 3 < NCHUNKS) LOAD_STAGE(c + 3, (c + 3) & 3);

        uint32_t soff = (uint32_t)s * TILE_BYTES;
#pragma unroll
        for (int ks = 0; ks < 2; ks++) {
            uint32_t a[2][4], b[4][4];
            uint32_t kb = soff + ks * 32;
            ldm_x4(a[0], a_base0 + kb);
            ldm_x4(a[1], a_base1 + kb);
#pragma unroll
            for (int jp = 0; jp < 4; jp++)
                ldm_x4(b[jp], b_base + kb + (uint32_t)(jp * 16 * 40) * 2);
#pragma unroll
            for (int ti = 0; ti < 2; ti++)
#pragma unroll
                for (int jp = 0; jp < 4; jp++) {
                    mma16816(acc[ti][jp * 2],     a[ti], b[jp][0], b[jp][1]);
                    mma16816(acc[ti][jp * 2 + 1], a[ti], b[jp][2], b[jp][3]);
                }
        }
    }
#undef LOAD_STAGE

    // ---------------- epilogue ----------------
    float scl = __ldg(scale_p);
    int lane4 = lane >> 2;
    int colp  = (lane & 3) * 2;

#pragma unroll
    for (int ti = 0; ti < 2; ti++) {
        int rA = m0 + wm * 32 + ti * 16 + lane4;
        int rB = rA + 8;
        bool okA = (rA < count), okB = (rB < count);
        float4 mtA = okA ? g_meta[rA] : make_float4(0.0f, 0.0f, 0.0f, 0.0f);
        float4 mtB = okB ? g_meta[rB] : make_float4(0.0f, 0.0f, 0.0f, 0.0f);
        int qA = (int)mtA.x, qB = (int)mtB.x;
        int mA = qA >> 2,  mB = qB >> 2;
        int catA = qA & 3, catB = qB & 3;
        const float* eA = g_E + (size_t)(catA * 3 + ((mA >> 1) % 3)) * 512;
        const float* eB = g_E + (size_t)(catB * 3 + ((mB >> 1) % 3)) * 512;
        int bA = mA / 1200, rIA = mA - bA * 1200;
        int bB = mB / 1200, rIB = mB - bB * 1200;
        float* oA = out + ((size_t)bA * RPB + 600 + rIA) * 512;
        float* oB = out + ((size_t)bB * RPB + 600 + rIB) * 512;

#pragma unroll
        for (int j = 0; j < 8; j++) {
            int n = n0 + wn * 64 + j * 8 + colp;
            float4 t0 = g_T4[n], t1 = g_T4[n + 1];
            if (okA) {
                float v0 = (acc[ti][j][0] + eA[n]     + mtA.y * t0.x + mtA.z * t0.y + mtA.w * t0.z) * scl;
                float v1 = (acc[ti][j][1] + eA[n + 1] + mtA.y * t1.x + mtA.z * t1.y + mtA.w * t1.z) * scl;
                *(float2*)(oA + n) = make_float2(v0, v1);
            }
            if (okB) {
                float u0 = (acc[ti][j][2] + eB[n]     + mtB.y * t0.x + mtB.z * t0.y + mtB.w * t0.z) * scl;
                float u1 = (acc[ti][j][3] + eB[n + 1] + mtB.y * t1.x + mtB.z * t1.y + mtB.w * t1.z) * scl;
                *(float2*)(oB + n) = make_float2(u0, u1);
            }
        }
    }
}

// ============================================================
extern "C" void kernel_launch(void* const* d_in, const int* in_sizes, int n_in,
                              void* d_out, int out_size)
{
    const float* box   = (const float*)d_in[0];
    const float* catT  = (const float*)d_in[1];
    const float* w1    = (const float*)d_in[2];
    const float* b1    = (const float*)d_in[3];
    const float* lng   = (const float*)d_in[4];
    const float* lnb   = (const float*)d_in[5];
    const float* w2    = (const float*)d_in[6];
    const float* b2    = (const float*)d_in[7];
    const float* confw = (const float*)d_in[8];
    const float* confb = (const float*)d_in[9];
    const float* cw    = (const float*)d_in[10];
    const float* cb    = (const float*)d_in[11];
    const float* miss  = (const float*)d_in[12];
    const float* dw    = (const float*)d_in[13];
    const float* db    = (const float*)d_in[14];
    const float* cam   = (const float*)d_in[15];
    const float* scale = (const float*)d_in[16];
    float* out = (float*)d_out;

    cudaFuncSetAttribute(gemm_kernel, cudaFuncAttributeMaxDynamicSharedMemorySize, SMEM_GEMM);

    aux_kernel<<<523, 512>>>(w2, b2, catT, confw, confb, cw, cb, miss, cam);
    prep_kernel<<<NBOXES / 8, 256>>>(box, w1, b1, lng, lnb, dw, db, miss, out);

    dim3 grid(4, NBOXES / 128);   // fixed worst-case; blocks past count exit
    gemm_kernel<<<grid, 256, SMEM_GEMM>>>(scale, out);
}

// round 8
// speedup vs baseline: 3.6936x; 1.2869x over previous
#include <cuda_runtime.h>
#include <cuda_fp16.h>
#include <math.h>
#include <stdint.h>

// Problem constants: B=128, T=200, NC=3, NB=2, D=512, DH=256
#define NBOXES  153600
#define GPB     600
#define RPB     1800

// ---------------- scratch ----------------
// Compacted A (present boxes only): [slot][0:256) = fp16(a)
__device__ __half  g_A[(size_t)NBOXES * 256];
// B[n][0:256) = fp16(w2[k][n]) (K-major per n)
__device__ __half  g_B[512 * 256];
__device__ float4  g_meta[NBOXES];   // per slot: {float(m*4+cat), conf, cx, cy}
__device__ float   g_E[9 * 512];     // b2+confb+cb+catT[c]+cam[v]
__device__ float4  g_T4[512];        // {confw, cw0, cw1, miss}
__device__ int     g_cnt;            // number of present boxes (compacted rows)

// ---------------- helpers ----------------
__device__ __forceinline__ uint32_t smem_u32(const void* p) {
    uint32_t a;
    asm("{ .reg .u64 t; cvta.to.shared.u64 t, %1; cvt.u32.u64 %0, t; }" : "=r"(a) : "l"(p));
    return a;
}
__device__ __forceinline__ void cpasync16(uint32_t s, const void* g) {
    asm volatile("cp.async.cg.shared.global [%0], [%1], 16;" :: "r"(s), "l"(g));
}
#define CP_COMMIT() asm volatile("cp.async.commit_group;" ::: "memory")
#define CP_WAIT(n)  asm volatile("cp.async.wait_group %0;" :: "n"(n) : "memory")

__device__ __forceinline__ void ldm_x4(uint32_t* r, uint32_t addr) {
    asm volatile("ldmatrix.sync.aligned.m8n8.x4.shared.b16 {%0,%1,%2,%3}, [%4];"
        : "=r"(r[0]), "=r"(r[1]), "=r"(r[2]), "=r"(r[3]) : "r"(addr));
}
__device__ __forceinline__ void mma16816(float* d, const uint32_t* a, uint32_t b0, uint32_t b1) {
    asm volatile(
        "mma.sync.aligned.m16n8k16.row.col.f32.f16.f16.f32 "
        "{%0,%1,%2,%3}, {%4,%5,%6,%7}, {%8,%9}, {%0,%1,%2,%3};"
        : "+f"(d[0]), "+f"(d[1]), "+f"(d[2]), "+f"(d[3])
        : "r"(a[0]), "r"(a[1]), "r"(a[2]), "r"(a[3]), "r"(b0), "r"(b1));
}

// ============================================================
// Kernel AUX: w2 fp16 convert (blocks 0..511), epilogue tables
// (blocks 512..521), counter reset (block 522). 512 threads.
// ============================================================
__global__ void aux_kernel(
    const float* __restrict__ w2,
    const float* __restrict__ b2,    const float* __restrict__ catT,
    const float* __restrict__ confw, const float* __restrict__ confb,
    const float* __restrict__ cw,    const float* __restrict__ cb,
    const float* __restrict__ miss,  const float* __restrict__ cam)
{
    int blk = blockIdx.x;
    int t = threadIdx.x;
    if (blk < 512) {
        if (t < 256) {
            int n = blk, k = t;
            float x = __ldg(w2 + (size_t)k * 512 + n);
            g_B[(size_t)n * 256 + k] = __float2half(x);
        }
    } else if (blk < 521) {
        int e = blk - 512;
        int n = t;
        int c = e / 3, v = e % 3;
        g_E[e * 512 + n] = __ldg(b2 + n) + __ldg(confb + n) + __ldg(cb + n)
                         + __ldg(catT + c * 512 + n) + __ldg(cam + v * 512 + n);
    } else if (blk == 521) {
        int n = t;
        g_T4[n] = make_float4(__ldg(confw + n), __ldg(cw + n),
                              __ldg(cw + 512 + n), __ldg(miss + n));
    } else {
        if (t == 0) g_cnt = 0;
    }
}

// ============================================================
// Kernel A: per-box prep (one warp per box), compaction of
// present boxes into g_A, direct missing_emb writes to out.
// ============================================================
__global__ void __launch_bounds__(256) prep_kernel(
    const float* __restrict__ box,
    const float* __restrict__ w1,  const float* __restrict__ b1,
    const float* __restrict__ lng, const float* __restrict__ lnb,
    const float* __restrict__ dw,  const float* __restrict__ db,
    const float* __restrict__ missv,
    float* __restrict__ out)
{
    __shared__ int s_pref[8];
    __shared__ int s_base;

    int wid  = threadIdx.x >> 5;
    int m    = blockIdx.x * 8 + wid;
    int lane = threadIdx.x & 31;
    int grp  = m >> 1;
    int jj   = m & 1;

    const float* p = box + (size_t)grp * 12;
    float r0[6], r1[6];
#pragma unroll
    for (int i = 0; i < 6; i++) { r0[i] = __ldg(p + i); r1[i] = __ldg(p + 6 + i); }

    const float inw = 1.0f / 640.0f, inh = 1.0f / 400.0f;
    float c0x1 = r0[0]*inw, c0y1 = r0[1]*inh, c0x2 = r0[2]*inw, c0y2 = r0[3]*inh;
    float c1x1 = r1[0]*inw, c1y1 = r1[1]*inh, c1x2 = r1[2]*inw, c1y2 = r1[3]*inh;
    float s0 = c0x1 + c0y1 + c0x2 + c0y2;
    float s1 = c1x1 + c1y1 + c1x2 + c1y2;
    float pr0 = (s0 != 0.0f) ? 1.0f : 0.0f;
    float pr1 = (s1 != 0.0f) ? 1.0f : 0.0f;
    float k0 = r0[4] + (1.0f - pr0) * 1000.0f;
    float k1 = r1[4] + (1.0f - pr1) * 1000.0f;
    bool swp = (k1 < k0);
    bool takeSecond = swp ? (jj == 0) : (jj == 1);

    float x1 = takeSecond ? c1x1 : c0x1;
    float y1 = takeSecond ? c1y1 : c0y1;
    float x2 = takeSecond ? c1x2 : c0x2;
    float y2 = takeSecond ? c1y2 : c0y2;
    float cat = takeSecond ? r1[4] : r0[4];
    float cf  = takeSecond ? r1[5] : r0[5];
    float pr  = takeSecond ? pr1  : pr0;
    bool present = (pr != 0.0f);

    // block-aggregated slot assignment (one atomic per block)
    if (lane == 0) s_pref[wid] = present ? 1 : 0;
    __syncthreads();
    if (threadIdx.x == 0) {
        int run = 0;
#pragma unroll
        for (int i = 0; i < 8; i++) { int v = s_pref[i]; s_pref[i] = run; run += v; }
        s_base = atomicAdd(&g_cnt, run);
    }
    __syncthreads();
    int slot = s_base + s_pref[wid];

    // output row base for this box
    int bI = m / 1200;
    int rI = m - bI * 1200;
    float* orow = out + ((size_t)bI * RPB + 600 + rI) * 512;

    if (present) {
        float w  = x2 - x1, hh = y2 - y1;
        float cx = (x1 + x2) * 0.5f, cy = (y1 + y2) * 0.5f;
        float area = w * hh;
        float asp  = w / (hh + 1e-6f);
        float ge[10] = {x1, y1, x2, y2, w, hh, cx, cy, area, asp};

        // lane handles dims d0..d0+3 for i in {0,1}: d0 = i*128 + lane*4
        float pre[8];
#pragma unroll
        for (int i = 0; i < 2; i++) {
            int d0 = i * 128 + lane * 4;
            float4 acc = *(const float4*)(b1 + d0);
#pragma unroll
            for (int k = 0; k < 10; k++) {
                float4 wv = __ldg((const float4*)(w1 + k * 256 + d0));
                acc.x = fmaf(ge[k], wv.x, acc.x);
                acc.y = fmaf(ge[k], wv.y, acc.y);
                acc.z = fmaf(ge[k], wv.z, acc.z);
                acc.w = fmaf(ge[k], wv.w, acc.w);
            }
            pre[i*4+0] = acc.x; pre[i*4+1] = acc.y;
            pre[i*4+2] = acc.z; pre[i*4+3] = acc.w;
        }
        float s = pre[0]+pre[1]+pre[2]+pre[3]+pre[4]+pre[5]+pre[6]+pre[7];
#pragma unroll
        for (int o = 16; o > 0; o >>= 1) s += __shfl_xor_sync(0xffffffffu, s, o);
        float mu = s * (1.0f / 256.0f);
        float v = 0.0f;
#pragma unroll
        for (int i = 0; i < 8; i++) { float d0 = pre[i] - mu; v = fmaf(d0, d0, v); }
#pragma unroll
        for (int o = 16; o > 0; o >>= 1) v += __shfl_xor_sync(0xffffffffu, v, o);
        float inv = rsqrtf(v * (1.0f / 256.0f) + 1e-5f);

        __half* arow = g_A + (size_t)slot * 256;
#pragma unroll
        for (int i = 0; i < 2; i++) {
            int d0 = i * 128 + lane * 4;
            float4 gv = *(const float4*)(lng + d0);
            float4 bv = *(const float4*)(lnb + d0);
            float gl[4];
#pragma unroll
            for (int j = 0; j < 4; j++) {
                float gg = (j==0)?gv.x:((j==1)?gv.y:((j==2)?gv.z:gv.w));
                float bb = (j==0)?bv.x:((j==1)?bv.y:((j==2)?bv.z:bv.w));
                float x = (pre[i*4+j] - mu) * inv * gg + bb;
                gl[j] = 0.5f * x * (1.0f + erff(x * 0.70710678118654752440f));
            }
            __half2 h01 = __floats2half2_rn(gl[0], gl[1]);
            __half2 h23 = __floats2half2_rn(gl[2], gl[3]);
            *(uint2*)(arow + d0) = make_uint2(*(uint32_t*)&h01, *(uint32_t*)&h23);
        }

        if (lane == 0) {
            g_meta[slot] = make_float4((float)(m * 4 + (int)cat), cf, cx, cy);
        }
    } else {
        // missing: write missing_emb row directly (unscaled, per reference)
#pragma unroll
        for (int i = 0; i < 4; i++) {
            int n = i * 128 + lane * 4;
            *(float4*)(orow + n) = __ldg((const float4*)(missv + n));
        }
    }

    // dist token row (one per group; invariant to the pair swap)
    if (jj == 0) {
        float cxa = (c0x1 + c0x2) * 0.5f, cya = (c0y1 + c0y2) * 0.5f;
        float cxb = (c1x1 + c1x2) * 0.5f, cyb = (c1y1 + c1y2) * 0.5f;
        float dx = cxa - cxb, dy = cya - cyb;
        float dist = sqrtf(dx * dx + dy * dy);
        float* drow = out + ((size_t)bI * RPB + (grp - bI * GPB)) * 512;
#pragma unroll
        for (int i = 0; i < 4; i++) {
            int n = i * 128 + lane * 4;
            float4 wv = __ldg((const float4*)(dw + n));
            float4 bv = __ldg((const float4*)(db + n));
            *(float4*)(drow + n) = make_float4(fmaf(dist, wv.x, bv.x), fmaf(dist, wv.y, bv.y),
                                               fmaf(dist, wv.z, bv.z), fmaf(dist, wv.w, bv.w));
        }
    }
}

// ============================================================
// Kernel G: fp16 mma.sync GEMM [count,256]x[256,512] on
// compacted rows + fused epilogue. BM=128, BN=128, BK=32,
// 8 warps, 4-stage cp.async pipeline. Fixed grid; early-exit.
// ============================================================
#define STAGES     4
#define TILE_ELEMS (128 * 40)
#define TILE_BYTES (TILE_ELEMS * 2)            // 10240
#define SMEM_GEMM  (2 * STAGES * TILE_BYTES)   // 81920
#define NCHUNKS    8                           // K = 256 / 32

__global__ void __launch_bounds__(256, 2) gemm_kernel(
    const float* __restrict__ scale_p, float* __restrict__ out)
{
    int count = g_cnt;
    int m0 = blockIdx.y * 128;
    if (m0 >= count) return;

    extern __shared__ __half smem_dyn[];
    uint32_t sbase = smem_u32(smem_dyn);
    uint32_t sbb   = sbase + STAGES * TILE_BYTES;

    int tid = threadIdx.x;
    int n0 = blockIdx.x * 128;
    int warp = tid >> 5, lane = tid & 31;
    int wm = warp >> 1, wn = warp & 1;

    int ldrow = tid >> 2, ldkc = (tid & 3) * 8;
    uint32_t aoff  = (uint32_t)(ldrow * 40 + ldkc) * 2;
    uint32_t aoff2 = (uint32_t)((ldrow + 64) * 40 + ldkc) * 2;

    float acc[2][8][4];
#pragma unroll
    for (int i = 0; i < 2; i++)
#pragma unroll
        for (int j = 0; j < 8; j++)
#pragma unroll
            for (int v = 0; v < 4; v++) acc[i][j][v] = 0.0f;

    int arow  = wm * 32 + (lane & 15);
    int acol8 = (lane >> 4) * 8;
    int brow  = wn * 64 + (lane & 7) + (lane >> 4) * 8;
    int bcol8 = ((lane >> 3) & 1) * 8;
    uint32_t a_base0 = sbase + (uint32_t)(arow * 40 + acol8) * 2;
    uint32_t a_base1 = sbase + (uint32_t)((arow + 16) * 40 + acol8) * 2;
    uint32_t b_base  = sbb   + (uint32_t)(brow * 40 + bcol8) * 2;

#define LOAD_STAGE(c, s) do {                                                    \
    const __half* gA = g_A + (size_t)(m0 + ldrow) * 256 + (c) * 32 + ldkc;       \
    const __half* gB = g_B + (size_t)(n0 + ldrow) * 256 + (c) * 32 + ldkc;       \
    uint32_t sA = sbase + (uint32_t)(s) * TILE_BYTES;                            \
    uint32_t sB = sbb   + (uint32_t)(s) * TILE_BYTES;                            \
    cpasync16(sA + aoff,  gA);                                                   \
    cpasync16(sA + aoff2, gA + (size_t)64 * 256);                                \
    cpasync16(sB + aoff,  gB);                                                   \
    cpasync16(sB + aoff2, gB + (size_t)64 * 256);                                \
    CP_COMMIT();                                                                 \
} while (0)

    LOAD_STAGE(0, 0);
    LOAD_STAGE(1, 1);
    LOAD_STAGE(2, 2);

#pragma unroll 4
    for (int c = 0; c < NCHUNKS; c++) {
        int s = c & 3;
        if (c < NCHUNKS - 2)       CP_WAIT(2);
        else if (c == NCHUNKS - 2) CP_WAIT(1);
        else                       CP_WAIT(0);
        __syncthreads();

        if (c + 3 < NCHUNKS) LOAD_STAGE(c + 3, (c + 3) & 3);

        uint32_t soff = (uint32_t)s * TILE_BYTES;
#pragma unroll
        for (int ks = 0; ks < 2; ks++) {
            uint32_t a[2][4], b[4][4];
            uint32_t kb = soff + ks * 32;
            ldm_x4(a[0], a_base0 + kb);
            ldm_x4(a[1], a_base1 + kb);
#pragma unroll
            for (int jp = 0; jp < 4; jp++)
                ldm_x4(b[jp], b_base + kb + (uint32_t)(jp * 16 * 40) * 2);
#pragma unroll
            for (int ti = 0; ti < 2; ti++)
#pragma unroll
                for (int jp = 0; jp < 4; jp++) {
                    mma16816(acc[ti][jp * 2],     a[ti], b[jp][0], b[jp][1]);
                    mma16816(acc[ti][jp * 2 + 1], a[ti], b[jp][2], b[jp][3]);
                }
        }
    }
#undef LOAD_STAGE

    // ---------------- epilogue ----------------
    float scl = __ldg(scale_p);
    int lane4 = lane >> 2;
    int colp  = (lane & 3) * 2;

#pragma unroll
    for (int ti = 0; ti < 2; ti++) {
        int rA = m0 + wm * 32 + ti * 16 + lane4;
        int rB = rA + 8;
        bool okA = (rA < count), okB = (rB < count);
        float4 mtA = okA ? g_meta[rA] : make_float4(0.0f, 0.0f, 0.0f, 0.0f);
        float4 mtB = okB ? g_meta[rB] : make_float4(0.0f, 0.0f, 0.0f, 0.0f);
        int qA = (int)mtA.x, qB = (int)mtB.x;
        int mA = qA >> 2,  mB = qB >> 2;
        int catA = qA & 3, catB = qB & 3;
        const float* eA = g_E + (size_t)(catA * 3 + ((mA >> 1) % 3)) * 512;
        const float* eB = g_E + (size_t)(catB * 3 + ((mB >> 1) % 3)) * 512;
        int bA = mA / 1200, rIA = mA - bA * 1200;
        int bB = mB / 1200, rIB = mB - bB * 1200;
        float* oA = out + ((size_t)bA * RPB + 600 + rIA) * 512;
        float* oB = out + ((size_t)bB * RPB + 600 + rIB) * 512;

#pragma unroll
        for (int j = 0; j < 8; j++) {
            int n = n0 + wn * 64 + j * 8 + colp;
            float4 t0 = g_T4[n], t1 = g_T4[n + 1];
            if (okA) {
                float v0 = (acc[ti][j][0] + eA[n]     + mtA.y * t0.x + mtA.z * t0.y + mtA.w * t0.z) * scl;
                float v1 = (acc[ti][j][1] + eA[n + 1] + mtA.y * t1.x + mtA.z * t1.y + mtA.w * t1.z) * scl;
                *(float2*)(oA + n) = make_float2(v0, v1);
            }
            if (okB) {
                float u0 = (acc[ti][j][2] + eB[n]     + mtB.y * t0.x + mtB.z * t0.y + mtB.w * t0.z) * scl;
                float u1 = (acc[ti][j][3] + eB[n + 1] + mtB.y * t1.x + mtB.z * t1.y + mtB.w * t1.z) * scl;
                *(float2*)(oB + n) = make_float2(u0, u1);
            }
        }
    }
}

// ============================================================
extern "C" void kernel_launch(void* const* d_in, const int* in_sizes, int n_in,
                              void* d_out, int out_size)
{
    const float* box   = (const float*)d_in[0];
    const float* catT  = (const float*)d_in[1];
    const float* w1    = (const float*)d_in[2];
    const float* b1    = (const float*)d_in[3];
    const float* lng   = (const float*)d_in[4];
    const float* lnb   = (const float*)d_in[5];
    const float* w2    = (const float*)d_in[6];
    const float* b2    = (const float*)d_in[7];
    const float* confw = (const float*)d_in[8];
    const float* confb = (const float*)d_in[9];
    const float* cw    = (const float*)d_in[10];
    const float* cb    = (const float*)d_in[11];
    const float* miss  = (const float*)d_in[12];
    const float* dw    = (const float*)d_in[13];
    const float* db    = (const float*)d_in[14];
    const float* cam   = (const float*)d_in[15];
    const float* scale = (const float*)d_in[16];
    float* out = (float*)d_out;

    cudaFuncSetAttribute(gemm_kernel, cudaFuncAttributeMaxDynamicSharedMemorySize, SMEM_GEMM);

    aux_kernel<<<523, 512>>>(w2, b2, catT, confw, confb, cw, cb, miss, cam);
    prep_kernel<<<NBOXES / 8, 256>>>(box, w1, b1, lng, lnb, dw, db, miss, out);

    dim3 grid(4, NBOXES / 128);   // fixed worst-case; blocks past count exit
    gemm_kernel<<<grid, 256, SMEM_GEMM>>>(scale, out);
}